// round 1
// baseline (speedup 1.0000x reference)
#include <cuda_runtime.h>
#include <math.h>

#define C_LEN 8192
#define Q_LEN 1024
#define D_DIM 1024

// ---------------- scratch (device globals; no allocations allowed) ----------
__device__ __align__(16) float g_e[C_LEN * Q_LEN];     // exp(s) (unnormalized softmax numerators)
__device__ __align__(16) float g_qterm[Q_LEN];
__device__ __align__(16) float g_cterm[C_LEN];
__device__ __align__(16) float g_bmax[C_LEN];
__device__ __align__(16) float g_colpart[16][Q_LEN];
__device__ __align__(16) float g_rz[Q_LEN];            // 1 / Z_q
__device__ __align__(16) float g_w[C_LEN];             // c2q softmax weights
__device__ __align__(16) float g_hpart[64][D_DIM];
__device__ __align__(16) float g_hrow[D_DIM];

// ---------------- q_term[q] = U[q,:]·w_q + b_q ------------------------------
__global__ void k_qterm(const float* __restrict__ U, const float* __restrict__ wq,
                        const float* __restrict__ bq) {
    const int n = blockIdx.x, t = threadIdx.x;
    float4 u = ((const float4*)U)[n * 256 + t];
    float4 w = ((const float4*)wq)[t];
    float p = u.x * w.x + u.y * w.y + u.z * w.z + u.w * w.w;
    __shared__ float sp[8];
#pragma unroll
    for (int o = 16; o; o >>= 1) p += __shfl_down_sync(0xffffffffu, p, o);
    if ((t & 31) == 0) sp[t >> 5] = p;
    __syncthreads();
    if (t == 0) {
        float s = sp[0];
#pragma unroll
        for (int i = 1; i < 8; ++i) s += sp[i];
        g_qterm[n] = s + bq[0];
    }
}

// ------------- c_term[c] = H[c,:]·w_c + b_c ;  bmax[c] = max_d H[c,d] --------
__global__ void k_rowstat(const float* __restrict__ H, const float* __restrict__ wc,
                          const float* __restrict__ bc) {
    const int c = blockIdx.x, t = threadIdx.x;
    float4 h = ((const float4*)H)[c * 256 + t];
    float4 w = ((const float4*)wc)[t];
    float p = h.x * w.x + h.y * w.y + h.z * w.z + h.w * w.w;
    float m = fmaxf(fmaxf(h.x, h.y), fmaxf(h.z, h.w));
    __shared__ float sp[8], sm2[8];
#pragma unroll
    for (int o = 16; o; o >>= 1) {
        p += __shfl_down_sync(0xffffffffu, p, o);
        m = fmaxf(m, __shfl_down_sync(0xffffffffu, m, o));
    }
    if ((t & 31) == 0) { sp[t >> 5] = p; sm2[t >> 5] = m; }
    __syncthreads();
    if (t == 0) {
        float pp = sp[0], mm = sm2[0];
#pragma unroll
        for (int i = 1; i < 8; ++i) { pp += sp[i]; mm = fmaxf(mm, sm2[i]); }
        g_cterm[c] = pp + bc[0];
        g_bmax[c] = mm;
    }
}

// ---------------- GEMM1 (NT): e = exp( (H∘wqc)·U^T + qterm + cterm + bqc ) --
__global__ __launch_bounds__(256, 2)
void k_gemm1(const float* __restrict__ A, const float* __restrict__ B,
             const float* __restrict__ wqc, const float* __restrict__ bqc) {
    __shared__ float As[16][128];
    __shared__ float Bs[16][128];
    __shared__ float swq[1024];

    const int tid = threadIdx.x;
    const int m0 = blockIdx.y * 128;
    const int n0 = blockIdx.x * 128;

    ((float4*)swq)[tid] = ((const float4*)wqc)[tid];

    const int lrow = tid >> 2;
    const int kb = (tid & 3) * 4;
    const int tx = tid & 15, ty = tid >> 4;

    const float* Ap0 = A + (m0 + lrow) * 1024 + kb;
    const float* Ap1 = Ap0 + 64 * 1024;
    const float* Bp0 = B + (n0 + lrow) * 1024 + kb;
    const float* Bp1 = Bp0 + 64 * 1024;

    float acc[8][8];
#pragma unroll
    for (int i = 0; i < 8; ++i)
#pragma unroll
        for (int j = 0; j < 8; ++j) acc[i][j] = 0.f;

    for (int k0 = 0; k0 < 1024; k0 += 16) {
        float4 a0 = *(const float4*)(Ap0 + k0);
        float4 a1 = *(const float4*)(Ap1 + k0);
        float4 b0 = *(const float4*)(Bp0 + k0);
        float4 b1 = *(const float4*)(Bp1 + k0);
        __syncthreads();
        const float w0 = swq[k0 + kb], w1 = swq[k0 + kb + 1],
                    w2 = swq[k0 + kb + 2], w3 = swq[k0 + kb + 3];
        As[kb + 0][lrow] = a0.x * w0;  As[kb + 1][lrow] = a0.y * w1;
        As[kb + 2][lrow] = a0.z * w2;  As[kb + 3][lrow] = a0.w * w3;
        As[kb + 0][lrow + 64] = a1.x * w0;  As[kb + 1][lrow + 64] = a1.y * w1;
        As[kb + 2][lrow + 64] = a1.z * w2;  As[kb + 3][lrow + 64] = a1.w * w3;
        Bs[kb + 0][lrow] = b0.x;  Bs[kb + 1][lrow] = b0.y;
        Bs[kb + 2][lrow] = b0.z;  Bs[kb + 3][lrow] = b0.w;
        Bs[kb + 0][lrow + 64] = b1.x;  Bs[kb + 1][lrow + 64] = b1.y;
        Bs[kb + 2][lrow + 64] = b1.z;  Bs[kb + 3][lrow + 64] = b1.w;
        __syncthreads();
#pragma unroll
        for (int kk = 0; kk < 16; ++kk) {
            float4 ra0 = *(const float4*)&As[kk][ty * 8];
            float4 ra1 = *(const float4*)&As[kk][ty * 8 + 4];
            float4 rb0 = *(const float4*)&Bs[kk][tx * 8];
            float4 rb1 = *(const float4*)&Bs[kk][tx * 8 + 4];
            const float av[8] = {ra0.x, ra0.y, ra0.z, ra0.w, ra1.x, ra1.y, ra1.z, ra1.w};
            const float bv[8] = {rb0.x, rb0.y, rb0.z, rb0.w, rb1.x, rb1.y, rb1.z, rb1.w};
#pragma unroll
            for (int i = 0; i < 8; ++i)
#pragma unroll
                for (int j = 0; j < 8; ++j) acc[i][j] = fmaf(av[i], bv[j], acc[i][j]);
        }
    }

    const float bq = bqc[0];
    float qt[8];
#pragma unroll
    for (int j = 0; j < 8; ++j) qt[j] = g_qterm[n0 + tx * 8 + j];
#pragma unroll
    for (int i = 0; i < 8; ++i) {
        const int m = m0 + ty * 8 + i;
        const float ct = g_cterm[m] + bq;
        float4 o0, o1;
        o0.x = expf(acc[i][0] + ct + qt[0]);
        o0.y = expf(acc[i][1] + ct + qt[1]);
        o0.z = expf(acc[i][2] + ct + qt[2]);
        o0.w = expf(acc[i][3] + ct + qt[3]);
        o1.x = expf(acc[i][4] + ct + qt[4]);
        o1.y = expf(acc[i][5] + ct + qt[5]);
        o1.z = expf(acc[i][6] + ct + qt[6]);
        o1.w = expf(acc[i][7] + ct + qt[7]);
        *(float4*)&g_e[m * 1024 + n0 + tx * 8] = o0;
        *(float4*)&g_e[m * 1024 + n0 + tx * 8 + 4] = o1;
    }
}

// ---------------- column sums Z_q (partials, deterministic) -----------------
__global__ void k_colsum() {
    const int q = blockIdx.x * 256 + threadIdx.x;
    const int c0 = blockIdx.y * 512;
    float s = 0.f;
    for (int c = c0; c < c0 + 512; ++c) s += g_e[c * 1024 + q];
    g_colpart[blockIdx.y][q] = s;
}

__global__ void k_colfin() {
    const int q = blockIdx.x * 256 + threadIdx.x;
    float s = 0.f;
#pragma unroll
    for (int i = 0; i < 16; ++i) s += g_colpart[i][q];
    g_rz[q] = 1.f / s;
}

// ---------------- GEMM2 (NN): U_toggler = (e ∘ rz_q) · U --------------------
__global__ __launch_bounds__(256, 2)
void k_gemm2(const float* __restrict__ B, float* __restrict__ out) {
    __shared__ float As[16][128];
    __shared__ float Bs[16][128];
    __shared__ float srz[1024];

    const int tid = threadIdx.x;
    const int m0 = blockIdx.y * 128;
    const int n0 = blockIdx.x * 128;

    ((float4*)srz)[tid] = ((const float4*)g_rz)[tid];

    const int lrow = tid >> 2;
    const int kb = (tid & 3) * 4;
    const int brow = tid >> 5;
    const int bcol = (tid & 31) * 4;
    const int tx = tid & 15, ty = tid >> 4;

    const float* Ap0 = g_e + (m0 + lrow) * 1024 + kb;
    const float* Ap1 = Ap0 + 64 * 1024;
    const float* Bp0 = B + brow * 1024 + n0 + bcol;

    float acc[8][8];
#pragma unroll
    for (int i = 0; i < 8; ++i)
#pragma unroll
        for (int j = 0; j < 8; ++j) acc[i][j] = 0.f;

    for (int k0 = 0; k0 < 1024; k0 += 16) {
        float4 a0 = *(const float4*)(Ap0 + k0);
        float4 a1 = *(const float4*)(Ap1 + k0);
        float4 b0 = *(const float4*)(Bp0 + k0 * 1024);
        float4 b1 = *(const float4*)(Bp0 + (k0 + 8) * 1024);
        __syncthreads();
        const float r0 = srz[k0 + kb], r1 = srz[k0 + kb + 1],
                    r2 = srz[k0 + kb + 2], r3 = srz[k0 + kb + 3];
        As[kb + 0][lrow] = a0.x * r0;  As[kb + 1][lrow] = a0.y * r1;
        As[kb + 2][lrow] = a0.z * r2;  As[kb + 3][lrow] = a0.w * r3;
        As[kb + 0][lrow + 64] = a1.x * r0;  As[kb + 1][lrow + 64] = a1.y * r1;
        As[kb + 2][lrow + 64] = a1.z * r2;  As[kb + 3][lrow + 64] = a1.w * r3;
        *(float4*)&Bs[brow][bcol] = b0;
        *(float4*)&Bs[brow + 8][bcol] = b1;
        __syncthreads();
#pragma unroll
        for (int kk = 0; kk < 16; ++kk) {
            float4 ra0 = *(const float4*)&As[kk][ty * 8];
            float4 ra1 = *(const float4*)&As[kk][ty * 8 + 4];
            float4 rb0 = *(const float4*)&Bs[kk][tx * 8];
            float4 rb1 = *(const float4*)&Bs[kk][tx * 8 + 4];
            const float av[8] = {ra0.x, ra0.y, ra0.z, ra0.w, ra1.x, ra1.y, ra1.z, ra1.w};
            const float bv[8] = {rb0.x, rb0.y, rb0.z, rb0.w, rb1.x, rb1.y, rb1.z, rb1.w};
#pragma unroll
            for (int i = 0; i < 8; ++i)
#pragma unroll
                for (int j = 0; j < 8; ++j) acc[i][j] = fmaf(av[i], bv[j], acc[i][j]);
        }
    }

#pragma unroll
    for (int i = 0; i < 8; ++i) {
        const int m = m0 + ty * 8 + i;
        float4 o0 = make_float4(acc[i][0], acc[i][1], acc[i][2], acc[i][3]);
        float4 o1 = make_float4(acc[i][4], acc[i][5], acc[i][6], acc[i][7]);
        *(float4*)&out[m * 1024 + n0 + tx * 8] = o0;
        *(float4*)&out[m * 1024 + n0 + tx * 8 + 4] = o1;
    }
}

// ---------------- c2q softmax over bmax[8192] --------------------------------
__global__ void k_c2q() {
    const int t = threadIdx.x;
    const int lane = t & 31, wid = t >> 5;
    __shared__ float sred[32];
    __shared__ float sbc[2];
    float m = -1e30f;
    for (int c = t; c < C_LEN; c += 1024) m = fmaxf(m, g_bmax[c]);
#pragma unroll
    for (int o = 16; o; o >>= 1) m = fmaxf(m, __shfl_xor_sync(0xffffffffu, m, o));
    if (lane == 0) sred[wid] = m;
    __syncthreads();
    if (t < 32) {
        float v = sred[t];
#pragma unroll
        for (int o = 16; o; o >>= 1) v = fmaxf(v, __shfl_xor_sync(0xffffffffu, v, o));
        if (t == 0) sbc[0] = v;
    }
    __syncthreads();
    const float mm = sbc[0];
    float z = 0.f;
    for (int c = t; c < C_LEN; c += 1024) z += expf(g_bmax[c] - mm);
#pragma unroll
    for (int o = 16; o; o >>= 1) z += __shfl_xor_sync(0xffffffffu, z, o);
    __syncthreads();
    if (lane == 0) sred[wid] = z;
    __syncthreads();
    if (t < 32) {
        float v = sred[t];
#pragma unroll
        for (int o = 16; o; o >>= 1) v += __shfl_xor_sync(0xffffffffu, v, o);
        if (t == 0) sbc[1] = v;
    }
    __syncthreads();
    const float rz = 1.f / sbc[1];
    for (int c = t; c < C_LEN; c += 1024) g_w[c] = expf(g_bmax[c] - mm) * rz;
}

// ---------------- weighted column sum of H (partials) -----------------------
__global__ void k_hpart(const float* __restrict__ H) {
    const int chunk = blockIdx.x, t = threadIdx.x;
    float a0 = 0.f, a1 = 0.f, a2 = 0.f, a3 = 0.f;
    const int c0 = chunk * 128;
    for (int c = c0; c < c0 + 128; ++c) {
        const float wv = g_w[c];
        const float* hr = H + c * 1024;
        a0 = fmaf(wv, hr[t], a0);
        a1 = fmaf(wv, hr[t + 256], a1);
        a2 = fmaf(wv, hr[t + 512], a2);
        a3 = fmaf(wv, hr[t + 768], a3);
    }
    g_hpart[chunk][t] = a0;
    g_hpart[chunk][t + 256] = a1;
    g_hpart[chunk][t + 512] = a2;
    g_hpart[chunk][t + 768] = a3;
}

__global__ void k_hred() {
    const int d = blockIdx.x * 256 + threadIdx.x;
    float s = 0.f;
#pragma unroll
    for (int i = 0; i < 64; ++i) s += g_hpart[i][d];
    g_hrow[d] = s;
}

// ---------------- broadcast H_toggler ----------------------------------------
__global__ void k_bcast(float* __restrict__ out) {
    const float4 v = ((const float4*)g_hrow)[threadIdx.x];
    ((float4*)(out + (size_t)C_LEN * D_DIM))[blockIdx.x * 256 + threadIdx.x] = v;
}

// ---------------- launch ------------------------------------------------------
extern "C" void kernel_launch(void* const* d_in, const int* in_sizes, int n_in,
                              void* d_out, int out_size) {
    const float* H   = (const float*)d_in[0];
    const float* U   = (const float*)d_in[1];
    const float* wq  = (const float*)d_in[2];
    const float* bq  = (const float*)d_in[3];
    const float* wc  = (const float*)d_in[4];
    const float* bc  = (const float*)d_in[5];
    const float* wqc = (const float*)d_in[6];
    const float* bqc = (const float*)d_in[7];
    float* out = (float*)d_out;

    k_qterm<<<Q_LEN, 256>>>(U, wq, bq);
    k_rowstat<<<C_LEN, 256>>>(H, wc, bc);
    k_gemm1<<<dim3(Q_LEN / 128, C_LEN / 128), 256>>>(H, U, wqc, bqc);
    k_colsum<<<dim3(4, 16), 256>>>();
    k_colfin<<<4, 256>>>();
    k_gemm2<<<dim3(D_DIM / 128, C_LEN / 128), 256>>>(U, out);
    k_c2q<<<1, 1024>>>();
    k_hpart<<<64, 256>>>(H);
    k_hred<<<4, 256>>>();
    k_bcast<<<C_LEN, 256>>>(out);
}

// round 3
// speedup vs baseline: 1.6874x; 1.6874x over previous
#include <cuda_runtime.h>
#include <cuda_bf16.h>
#include <cstdint>
#include <math.h>

#define C_LEN 8192
#define Q_LEN 1024
#define D_DIM 1024

// ---------------- scratch (device globals; no allocations allowed) ----------
__device__ __align__(16) __nv_bfloat16 g_eh[C_LEN * Q_LEN];   // exp(s) hi
__device__ __align__(16) __nv_bfloat16 g_el[C_LEN * Q_LEN];   // exp(s) lo
__device__ __align__(16) __nv_bfloat16 g_B2h[D_DIM * Q_LEN];  // (U*rz)^T hi
__device__ __align__(16) __nv_bfloat16 g_B2l[D_DIM * Q_LEN];  // (U*rz)^T lo
__device__ __align__(16) float g_qterm[Q_LEN];
__device__ __align__(16) float g_cterm[C_LEN];
__device__ __align__(16) float g_bmax[C_LEN];
__device__ __align__(16) float g_colpart[64 * Q_LEN];
__device__ __align__(16) float g_rz[Q_LEN];
__device__ __align__(16) float g_w[C_LEN];
__device__ __align__(16) float g_hpart[64][D_DIM];
__device__ __align__(16) float g_hrow[D_DIM];

// ---------------- helpers -----------------------------------------------------
__device__ __forceinline__ uint32_t pack_lo_bf16x2(float l0, float l1) {
    uint32_t r;
    asm("cvt.rn.bf16x2.f32 %0, %1, %2;" : "=r"(r) : "f"(l1), "f"(l0));
    return r;
}
// split 4 floats -> 2 hi-bf16x2 words (truncate) + 2 lo-bf16x2 words (residual)
__device__ __forceinline__ void split4(float x, float y, float z, float w,
                                       uint32_t& h0, uint32_t& h1,
                                       uint32_t& l0, uint32_t& l1) {
    uint32_t bx = __float_as_uint(x), by = __float_as_uint(y);
    uint32_t bz = __float_as_uint(z), bw = __float_as_uint(w);
    h0 = __byte_perm(bx, by, 0x7632);
    h1 = __byte_perm(bz, bw, 0x7632);
    l0 = pack_lo_bf16x2(x - __uint_as_float(bx & 0xffff0000u),
                        y - __uint_as_float(by & 0xffff0000u));
    l1 = pack_lo_bf16x2(z - __uint_as_float(bz & 0xffff0000u),
                        w - __uint_as_float(bw & 0xffff0000u));
}

__device__ __forceinline__ void mma16816(float4& c, const uint32_t a[4], const uint32_t b[2]) {
    asm volatile(
        "mma.sync.aligned.m16n8k16.row.col.f32.bf16.bf16.f32 "
        "{%0,%1,%2,%3}, {%4,%5,%6,%7}, {%8,%9}, {%0,%1,%2,%3};"
        : "+f"(c.x), "+f"(c.y), "+f"(c.z), "+f"(c.w)
        : "r"(a[0]), "r"(a[1]), "r"(a[2]), "r"(a[3]), "r"(b[0]), "r"(b[1]));
}

// ---------------- q_term / rowstat --------------------------------------------
__global__ void k_qterm(const float* __restrict__ U, const float* __restrict__ wq,
                        const float* __restrict__ bq) {
    const int n = blockIdx.x, t = threadIdx.x;
    float4 u = ((const float4*)U)[n * 256 + t];
    float4 w = ((const float4*)wq)[t];
    float p = u.x * w.x + u.y * w.y + u.z * w.z + u.w * w.w;
    __shared__ float sp[8];
#pragma unroll
    for (int o = 16; o; o >>= 1) p += __shfl_down_sync(0xffffffffu, p, o);
    if ((t & 31) == 0) sp[t >> 5] = p;
    __syncthreads();
    if (t == 0) {
        float s = sp[0];
#pragma unroll
        for (int i = 1; i < 8; ++i) s += sp[i];
        g_qterm[n] = s + bq[0];
    }
}

__global__ void k_rowstat(const float* __restrict__ H, const float* __restrict__ wc,
                          const float* __restrict__ bc) {
    const int c = blockIdx.x, t = threadIdx.x;
    float4 h = ((const float4*)H)[c * 256 + t];
    float4 w = ((const float4*)wc)[t];
    float p = h.x * w.x + h.y * w.y + h.z * w.z + h.w * w.w;
    float m = fmaxf(fmaxf(h.x, h.y), fmaxf(h.z, h.w));
    __shared__ float sp[8], sm2[8];
#pragma unroll
    for (int o = 16; o; o >>= 1) {
        p += __shfl_down_sync(0xffffffffu, p, o);
        m = fmaxf(m, __shfl_down_sync(0xffffffffu, m, o));
    }
    if ((t & 31) == 0) { sp[t >> 5] = p; sm2[t >> 5] = m; }
    __syncthreads();
    if (t == 0) {
        float pp = sp[0], mm = sm2[0];
#pragma unroll
        for (int i = 1; i < 8; ++i) { pp += sp[i]; mm = fmaxf(mm, sm2[i]); }
        g_cterm[c] = pp + bc[0];
        g_bmax[c] = mm;
    }
}

// ---------------- coalesced transpose + split: B2 = (U * rz)^T ---------------
__global__ void k_prep_ut(const float* __restrict__ U) {
    __shared__ float t[32][33];
    const int tx = threadIdx.x & 31, ty = threadIdx.x >> 5;  // 32 x 8
    const int d0 = blockIdx.x * 32, q0 = blockIdx.y * 32;
#pragma unroll
    for (int i = 0; i < 4; ++i)
        t[ty + 8 * i][tx] = U[(size_t)(q0 + ty + 8 * i) * 1024 + d0 + tx];
    __syncthreads();
#pragma unroll
    for (int i = 0; i < 4; ++i) {
        const int d = d0 + ty + 8 * i;
        const int q = q0 + tx;
        const float v = t[tx][ty + 8 * i] * g_rz[q];
        const uint32_t b = __float_as_uint(v);
        ((uint16_t*)g_B2h)[(size_t)d * 1024 + q] = (uint16_t)(b >> 16);
        const float l = v - __uint_as_float(b & 0xffff0000u);
        ((__nv_bfloat16*)g_B2l)[(size_t)d * 1024 + q] = __float2bfloat16(l);
    }
}

// ---------------- GEMM via mma.sync (fallback HMMA), 3xBF16 split ------------
// Stage buffers: per stage Ah | Al | Bh | Bl, each 128 rows x 48B (16 bf16 + pad)
// PASS=1: e = exp((H wqc U^T) + qterm + cterm + bqc) -> g_eh/g_el + colsums
// PASS=2: out = (eh+el) @ (B2h+B2l)^T
#define T_OFF_AL 6144
#define T_OFF_BH 12288
#define T_OFF_BL 18432
#define T_STAGE  24576

template <int PASS>
__device__ __forceinline__ void ld_gmem(const float* __restrict__ Af,
                                        const float* __restrict__ Bf,
                                        const float* __restrict__ wqc,
                                        int m0, int n0, int k0,
                                        int lrow, int lc4, uint32_t r[8]) {
    if (PASS == 1) {
        const float4 a = *(const float4*)(Af + (size_t)(m0 + lrow) * 1024 + k0 + lc4 * 4);
        const float4 w = *(const float4*)(wqc + k0 + lc4 * 4);
        float4 b = *(const float4*)(Bf + (size_t)(n0 + lrow) * 1024 + k0 + lc4 * 4);
        b.x *= w.x; b.y *= w.y; b.z *= w.z; b.w *= w.w;
        split4(a.x, a.y, a.z, a.w, r[0], r[1], r[2], r[3]);
        split4(b.x, b.y, b.z, b.w, r[4], r[5], r[6], r[7]);
    } else {
        const size_t oa = (size_t)(m0 + lrow) * 1024 + k0 + lc4 * 4;
        const uint2 ah = *(const uint2*)((const uint16_t*)g_eh + oa);
        const uint2 al = *(const uint2*)((const uint16_t*)g_el + oa);
        const size_t ob = (size_t)(n0 + lrow) * 1024 + k0 + lc4 * 4;
        const uint2 bh = *(const uint2*)((const uint16_t*)g_B2h + ob);
        const uint2 bl = *(const uint2*)((const uint16_t*)g_B2l + ob);
        r[0] = ah.x; r[1] = ah.y; r[2] = al.x; r[3] = al.y;
        r[4] = bh.x; r[5] = bh.y; r[6] = bl.x; r[7] = bl.y;
    }
}

__device__ __forceinline__ void st_stage(char* buf, int lrow, int lc4, const uint32_t r[8]) {
    const int o = lrow * 48 + lc4 * 8;
    *(uint32_t*)(buf + o) = r[0];
    *(uint32_t*)(buf + o + 4) = r[1];
    *(uint32_t*)(buf + T_OFF_AL + o) = r[2];
    *(uint32_t*)(buf + T_OFF_AL + o + 4) = r[3];
    *(uint32_t*)(buf + T_OFF_BH + o) = r[4];
    *(uint32_t*)(buf + T_OFF_BH + o + 4) = r[5];
    *(uint32_t*)(buf + T_OFF_BL + o) = r[6];
    *(uint32_t*)(buf + T_OFF_BL + o + 4) = r[7];
}

template <int PASS>
__global__ __launch_bounds__(512, 1)
void k_mma(const float* __restrict__ Af, const float* __restrict__ Bf,
           const float* __restrict__ wqc, const float* __restrict__ bqc,
           float* __restrict__ out) {
    extern __shared__ char sm[];
    const int tid = threadIdx.x;
    const int lane = tid & 31, wid = tid >> 5;
    const int wm = wid & 3, wn = wid >> 2;
    const int g = lane >> 2, tq = lane & 3;
    const int m0 = blockIdx.y * 128, n0 = blockIdx.x * 128;
    const int lrow = tid >> 2, lc4 = tid & 3;

    float4 acc[2][4];
#pragma unroll
    for (int i = 0; i < 2; ++i)
#pragma unroll
        for (int j = 0; j < 4; ++j) acc[i][j] = make_float4(0.f, 0.f, 0.f, 0.f);

    uint32_t r[8];
    ld_gmem<PASS>(Af, Bf, wqc, m0, n0, 0, lrow, lc4, r);
    st_stage(sm, lrow, lc4, r);
    __syncthreads();

#pragma unroll 2
    for (int s = 0; s < 64; ++s) {
        if (s < 63) ld_gmem<PASS>(Af, Bf, wqc, m0, n0, (s + 1) * 16, lrow, lc4, r);

        char* buf = sm + (s & 1) * T_STAGE;
        uint32_t ah[2][4], al[2][4], bh[4][2], bl[4][2];
#pragma unroll
        for (int mt = 0; mt < 2; ++mt) {
            const int ra = (wm * 32 + mt * 16 + g) * 48 + tq * 4;
            ah[mt][0] = *(const uint32_t*)(buf + ra);
            ah[mt][1] = *(const uint32_t*)(buf + ra + 384);
            ah[mt][2] = *(const uint32_t*)(buf + ra + 16);
            ah[mt][3] = *(const uint32_t*)(buf + ra + 400);
            al[mt][0] = *(const uint32_t*)(buf + T_OFF_AL + ra);
            al[mt][1] = *(const uint32_t*)(buf + T_OFF_AL + ra + 384);
            al[mt][2] = *(const uint32_t*)(buf + T_OFF_AL + ra + 16);
            al[mt][3] = *(const uint32_t*)(buf + T_OFF_AL + ra + 400);
        }
#pragma unroll
        for (int nt = 0; nt < 4; ++nt) {
            const int rb = (wn * 32 + nt * 8 + g) * 48 + tq * 4;
            bh[nt][0] = *(const uint32_t*)(buf + T_OFF_BH + rb);
            bh[nt][1] = *(const uint32_t*)(buf + T_OFF_BH + rb + 16);
            bl[nt][0] = *(const uint32_t*)(buf + T_OFF_BL + rb);
            bl[nt][1] = *(const uint32_t*)(buf + T_OFF_BL + rb + 16);
        }
#pragma unroll
        for (int mt = 0; mt < 2; ++mt)
#pragma unroll
            for (int nt = 0; nt < 4; ++nt) {
                mma16816(acc[mt][nt], ah[mt], bh[nt]);
                mma16816(acc[mt][nt], ah[mt], bl[nt]);
                mma16816(acc[mt][nt], al[mt], bh[nt]);
            }

        if (s < 63) {
            st_stage(sm + ((s + 1) & 1) * T_STAGE, lrow, lc4, r);
            __syncthreads();
        }
    }
    __syncthreads();

    if (PASS == 1) {
        const float bq = bqc[0];
        float* s_cp = (float*)sm;  // [4][128], overlays stage buffers (done with them)
        float cs[4][2];
#pragma unroll
        for (int nt = 0; nt < 4; ++nt) { cs[nt][0] = 0.f; cs[nt][1] = 0.f; }
#pragma unroll
        for (int mt = 0; mt < 2; ++mt) {
            const int row = m0 + wm * 32 + mt * 16 + g;
            const float ct0 = g_cterm[row], ct1 = g_cterm[row + 8];
#pragma unroll
            for (int nt = 0; nt < 4; ++nt) {
                const int col = n0 + wn * 32 + nt * 8 + tq * 2;
                const float q0 = g_qterm[col] + bq, q1 = g_qterm[col + 1] + bq;
                const float4 c = acc[mt][nt];
                const float e00 = __expf(c.x + ct0 + q0), e01 = __expf(c.y + ct0 + q1);
                const float e10 = __expf(c.z + ct1 + q0), e11 = __expf(c.w + ct1 + q1);
                uint32_t h0, h1, l0, l1;
                split4(e00, e01, e10, e11, h0, h1, l0, l1);
                const size_t o0 = (size_t)row * 1024 + col;
                const size_t o1 = (size_t)(row + 8) * 1024 + col;
                *(uint32_t*)((uint16_t*)g_eh + o0) = h0;
                *(uint32_t*)((uint16_t*)g_el + o0) = l0;
                *(uint32_t*)((uint16_t*)g_eh + o1) = h1;
                *(uint32_t*)((uint16_t*)g_el + o1) = l1;
                cs[nt][0] += e00 + e10;
                cs[nt][1] += e01 + e11;
            }
        }
#pragma unroll
        for (int nt = 0; nt < 4; ++nt)
#pragma unroll
            for (int o = 4; o < 32; o <<= 1) {
                cs[nt][0] += __shfl_xor_sync(0xffffffffu, cs[nt][0], o);
                cs[nt][1] += __shfl_xor_sync(0xffffffffu, cs[nt][1], o);
            }
        if (g == 0) {
#pragma unroll
            for (int nt = 0; nt < 4; ++nt) {
                const int col = wn * 32 + nt * 8 + tq * 2;
                s_cp[wm * 128 + col] = cs[nt][0];
                s_cp[wm * 128 + col + 1] = cs[nt][1];
            }
        }
        __syncthreads();
        if (tid < 128) {
            const float v = s_cp[tid] + s_cp[128 + tid] + s_cp[256 + tid] + s_cp[384 + tid];
            g_colpart[blockIdx.y * 1024 + n0 + tid] = v;
        }
    } else {
#pragma unroll
        for (int mt = 0; mt < 2; ++mt) {
            const int row = m0 + wm * 32 + mt * 16 + g;
#pragma unroll
            for (int nt = 0; nt < 4; ++nt) {
                const int col = n0 + wn * 32 + nt * 8 + tq * 2;
                const float4 c = acc[mt][nt];
                *(float2*)(out + (size_t)row * 1024 + col) = make_float2(c.x, c.y);
                *(float2*)(out + (size_t)(row + 8) * 1024 + col) = make_float2(c.z, c.w);
            }
        }
    }
}

// ---------------- Z_q reduction ------------------------------------------------
__global__ void k_colfin() {
    const int q = blockIdx.x * 256 + threadIdx.x;
    float s = 0.f;
#pragma unroll
    for (int i = 0; i < 64; ++i) s += g_colpart[i * 1024 + q];
    g_rz[q] = 1.f / s;
}

// ---------------- c2q softmax over bmax[8192] ----------------------------------
__global__ void k_c2q() {
    const int t = threadIdx.x;
    const int lane = t & 31, wid = t >> 5;
    __shared__ float sred[32];
    __shared__ float sbc[2];
    float m = -1e30f;
    for (int c = t; c < C_LEN; c += 1024) m = fmaxf(m, g_bmax[c]);
#pragma unroll
    for (int o = 16; o; o >>= 1) m = fmaxf(m, __shfl_xor_sync(0xffffffffu, m, o));
    if (lane == 0) sred[wid] = m;
    __syncthreads();
    if (t < 32) {
        float v = sred[t];
#pragma unroll
        for (int o = 16; o; o >>= 1) v = fmaxf(v, __shfl_xor_sync(0xffffffffu, v, o));
        if (t == 0) sbc[0] = v;
    }
    __syncthreads();
    const float mm = sbc[0];
    float z = 0.f;
    for (int c = t; c < C_LEN; c += 1024) z += expf(g_bmax[c] - mm);
#pragma unroll
    for (int o = 16; o; o >>= 1) z += __shfl_xor_sync(0xffffffffu, z, o);
    __syncthreads();
    if (lane == 0) sred[wid] = z;
    __syncthreads();
    if (t < 32) {
        float v = sred[t];
#pragma unroll
        for (int o = 16; o; o >>= 1) v += __shfl_xor_sync(0xffffffffu, v, o);
        if (t == 0) sbc[1] = v;
    }
    __syncthreads();
    const float rz = 1.f / sbc[1];
    for (int c = t; c < C_LEN; c += 1024) g_w[c] = expf(g_bmax[c] - mm) * rz;
}

// ---------------- weighted column sum of H --------------------------------------
__global__ void k_hpart(const float* __restrict__ H) {
    const int chunk = blockIdx.x, t = threadIdx.x;
    float a0 = 0.f, a1 = 0.f, a2 = 0.f, a3 = 0.f;
    const int c0 = chunk * 128;
    for (int c = c0; c < c0 + 128; ++c) {
        const float wv = g_w[c];
        const float* hr = H + (size_t)c * 1024;
        a0 = fmaf(wv, hr[t], a0);
        a1 = fmaf(wv, hr[t + 256], a1);
        a2 = fmaf(wv, hr[t + 512], a2);
        a3 = fmaf(wv, hr[t + 768], a3);
    }
    g_hpart[chunk][t] = a0;
    g_hpart[chunk][t + 256] = a1;
    g_hpart[chunk][t + 512] = a2;
    g_hpart[chunk][t + 768] = a3;
}

__global__ void k_hred() {
    const int d = blockIdx.x * 256 + threadIdx.x;
    float s = 0.f;
#pragma unroll
    for (int i = 0; i < 64; ++i) s += g_hpart[i][d];
    g_hrow[d] = s;
}

__global__ void k_bcast(float* __restrict__ out) {
    const float4 v = ((const float4*)g_hrow)[threadIdx.x];
    ((float4*)(out + (size_t)C_LEN * D_DIM))[blockIdx.x * 256 + threadIdx.x] = v;
}

// ---------------- launch ---------------------------------------------------------
extern "C" void kernel_launch(void* const* d_in, const int* in_sizes, int n_in,
                              void* d_out, int out_size) {
    const float* H   = (const float*)d_in[0];
    const float* U   = (const float*)d_in[1];
    const float* wq  = (const float*)d_in[2];
    const float* bq  = (const float*)d_in[3];
    const float* wc  = (const float*)d_in[4];
    const float* bc  = (const float*)d_in[5];
    const float* wqc = (const float*)d_in[6];
    const float* bqc = (const float*)d_in[7];
    float* out = (float*)d_out;

    k_qterm<<<Q_LEN, 256>>>(U, wq, bq);
    k_rowstat<<<C_LEN, 256>>>(H, wc, bc);
    k_mma<1><<<dim3(8, 64), 512, 49152>>>(H, U, wqc, bqc, nullptr);
    k_colfin<<<4, 256>>>();
    k_prep_ut<<<dim3(32, 32), 256>>>(U);
    k_mma<2><<<dim3(8, 64), 512, 49152>>>(nullptr, nullptr, wqc, bqc, out);
    k_c2q<<<1, 1024>>>();
    k_hpart<<<64, 256>>>(H);
    k_hred<<<4, 256>>>();
    k_bcast<<<C_LEN, 256>>>(out);
}

// round 4
// speedup vs baseline: 2.0364x; 1.2068x over previous
#include <cuda_runtime.h>
#include <cuda_bf16.h>
#include <cstdint>
#include <math.h>

#define C_LEN 8192
#define Q_LEN 1024
#define D_DIM 1024

// ---------------- scratch (device globals) -----------------------------------
__device__ __align__(16) __nv_bfloat16 g_Hh[C_LEN * D_DIM];
__device__ __align__(16) __nv_bfloat16 g_Hl[C_LEN * D_DIM];
__device__ __align__(16) __nv_bfloat16 g_B1h[Q_LEN * D_DIM];
__device__ __align__(16) __nv_bfloat16 g_B1l[Q_LEN * D_DIM];
__device__ __align__(16) __nv_bfloat16 g_B2h[D_DIM * Q_LEN];
__device__ __align__(16) __nv_bfloat16 g_B2l[D_DIM * Q_LEN];
__device__ __align__(16) __nv_bfloat16 g_eh[C_LEN * Q_LEN];
__device__ __align__(16) __nv_bfloat16 g_el[C_LEN * Q_LEN];
__device__ __align__(16) float g_qterm[Q_LEN];
__device__ __align__(16) float g_cterm[C_LEN];
__device__ __align__(16) float g_bmax[C_LEN];
__device__ __align__(16) float g_colpart[64 * Q_LEN];
__device__ __align__(16) float g_rz[Q_LEN];
__device__ __align__(16) float g_w[C_LEN];
__device__ __align__(16) float g_hpart[64][D_DIM];
__device__ __align__(16) float g_hrow[D_DIM];

// ---------------- helpers -----------------------------------------------------
__device__ __forceinline__ uint32_t smem_u32(const void* p) {
    uint32_t a;
    asm("{ .reg .u64 t; cvta.to.shared.u64 t, %1; cvt.u32.u64 %0, t; }" : "=r"(a) : "l"(p));
    return a;
}
__device__ __forceinline__ uint32_t pack_lo_bf16x2(float l0, float l1) {
    uint32_t r;
    asm("cvt.rn.bf16x2.f32 %0, %1, %2;" : "=r"(r) : "f"(l1), "f"(l0));
    return r;
}
__device__ __forceinline__ void split4(float x, float y, float z, float w,
                                       uint32_t& h0, uint32_t& h1,
                                       uint32_t& l0, uint32_t& l1) {
    uint32_t bx = __float_as_uint(x), by = __float_as_uint(y);
    uint32_t bz = __float_as_uint(z), bw = __float_as_uint(w);
    h0 = __byte_perm(bx, by, 0x7632);
    h1 = __byte_perm(bz, bw, 0x7632);
    l0 = pack_lo_bf16x2(x - __uint_as_float(bx & 0xffff0000u),
                        y - __uint_as_float(by & 0xffff0000u));
    l1 = pack_lo_bf16x2(z - __uint_as_float(bz & 0xffff0000u),
                        w - __uint_as_float(bw & 0xffff0000u));
}
__device__ __forceinline__ void mma16816(float4& c, const uint32_t a[4],
                                         uint32_t b0, uint32_t b1) {
    asm volatile(
        "mma.sync.aligned.m16n8k16.row.col.f32.bf16.bf16.f32 "
        "{%0,%1,%2,%3}, {%4,%5,%6,%7}, {%8,%9}, {%0,%1,%2,%3};"
        : "+f"(c.x), "+f"(c.y), "+f"(c.z), "+f"(c.w)
        : "r"(a[0]), "r"(a[1]), "r"(a[2]), "r"(a[3]), "r"(b0), "r"(b1));
}
__device__ __forceinline__ void ldsm4(uint32_t d[4], uint32_t a) {
    asm volatile("ldmatrix.sync.aligned.m8n8.x4.shared.b16 {%0,%1,%2,%3}, [%4];"
                 : "=r"(d[0]), "=r"(d[1]), "=r"(d[2]), "=r"(d[3]) : "r"(a));
}
#define CP_ASYNC(d, s) asm volatile("cp.async.ca.shared.global [%0], [%1], 16;" :: "r"(d), "l"(s) : "memory")
#define CP_COMMIT()    asm volatile("cp.async.commit_group;" ::: "memory")
#define CP_WAIT2()     asm volatile("cp.async.wait_group 2;" ::: "memory")

// ---------------- q_term / rowstat --------------------------------------------
__global__ void k_qterm(const float* __restrict__ U, const float* __restrict__ wq,
                        const float* __restrict__ bq) {
    const int n = blockIdx.x, t = threadIdx.x;
    float4 u = ((const float4*)U)[n * 256 + t];
    float4 w = ((const float4*)wq)[t];
    float p = u.x * w.x + u.y * w.y + u.z * w.z + u.w * w.w;
    __shared__ float sp[8];
#pragma unroll
    for (int o = 16; o; o >>= 1) p += __shfl_down_sync(0xffffffffu, p, o);
    if ((t & 31) == 0) sp[t >> 5] = p;
    __syncthreads();
    if (t == 0) {
        float s = sp[0];
#pragma unroll
        for (int i = 1; i < 8; ++i) s += sp[i];
        g_qterm[n] = s + bq[0];
    }
}

__global__ void k_rowstat(const float* __restrict__ H, const float* __restrict__ wc,
                          const float* __restrict__ bc) {
    const int c = blockIdx.x, t = threadIdx.x;
    float4 h = ((const float4*)H)[c * 256 + t];
    float4 w = ((const float4*)wc)[t];
    float p = h.x * w.x + h.y * w.y + h.z * w.z + h.w * w.w;
    float m = fmaxf(fmaxf(h.x, h.y), fmaxf(h.z, h.w));
    __shared__ float sp[8], sm2[8];
#pragma unroll
    for (int o = 16; o; o >>= 1) {
        p += __shfl_down_sync(0xffffffffu, p, o);
        m = fmaxf(m, __shfl_down_sync(0xffffffffu, m, o));
    }
    if ((t & 31) == 0) { sp[t >> 5] = p; sm2[t >> 5] = m; }
    __syncthreads();
    if (t == 0) {
        float pp = sp[0], mm = sm2[0];
#pragma unroll
        for (int i = 1; i < 8; ++i) { pp += sp[i]; mm = fmaxf(mm, sm2[i]); }
        g_cterm[c] = pp + bc[0];
        g_bmax[c] = mm;
    }
}

// ---------------- prep: split H -----------------------------------------------
__global__ void k_prep_h(const float* __restrict__ H) {
    const int i = (blockIdx.x * 256 + threadIdx.x) * 4;
    float4 a = *(const float4*)(H + i);
    uint32_t h0, h1, l0, l1;
    split4(a.x, a.y, a.z, a.w, h0, h1, l0, l1);
    *(uint2*)((uint16_t*)g_Hh + i) = make_uint2(h0, h1);
    *(uint2*)((uint16_t*)g_Hl + i) = make_uint2(l0, l1);
}

// ---------------- prep: split (U * wqc) ----------------------------------------
__global__ void k_prep_uw(const float* __restrict__ U, const float* __restrict__ wqc) {
    const int q = blockIdx.x, t = threadIdx.x;
    const int i = q * 1024 + t * 4;
    float4 a = *(const float4*)(U + i);
    float4 w = ((const float4*)wqc)[t];
    a.x *= w.x; a.y *= w.y; a.z *= w.z; a.w *= w.w;
    uint32_t h0, h1, l0, l1;
    split4(a.x, a.y, a.z, a.w, h0, h1, l0, l1);
    *(uint2*)((uint16_t*)g_B1h + i) = make_uint2(h0, h1);
    *(uint2*)((uint16_t*)g_B1l + i) = make_uint2(l0, l1);
}

// ---------------- prep: transpose+split (U * rz)^T -----------------------------
__global__ void k_prep_ut(const float* __restrict__ U) {
    __shared__ float t[32][33];
    const int tx = threadIdx.x & 31, ty = threadIdx.x >> 5;
    const int d0 = blockIdx.x * 32, q0 = blockIdx.y * 32;
#pragma unroll
    for (int i = 0; i < 4; ++i)
        t[ty + 8 * i][tx] = U[(size_t)(q0 + ty + 8 * i) * 1024 + d0 + tx];
    __syncthreads();
#pragma unroll
    for (int i = 0; i < 4; ++i) {
        const int d = d0 + ty + 8 * i;
        const int q = q0 + tx;
        const float v = t[tx][ty + 8 * i] * g_rz[q];
        const uint32_t b = __float_as_uint(v);
        ((uint16_t*)g_B2h)[(size_t)d * 1024 + q] = (uint16_t)(b >> 16);
        const float l = v - __uint_as_float(b & 0xffff0000u);
        ((__nv_bfloat16*)g_B2l)[(size_t)d * 1024 + q] = __float2bfloat16(l);
    }
}

// ---------------- GEMM: cp.async 3-stage + ldmatrix + 3xBF16 ------------------
// stage = Ah | Al | Bh | Bl, each 128 rows x 64B (K=32 bf16), XOR-swizzled chunks
#define ST_AL 8192u
#define ST_BH 16384u
#define ST_BL 24576u
#define ST_SZ 32768u

__device__ __forceinline__ void fill_stage(uint32_t sb,
                                           const __nv_bfloat16* Ah, const __nv_bfloat16* Al,
                                           const __nv_bfloat16* Bh, const __nv_bfloat16* Bl,
                                           int m0, int n0, int k0, int cr, int cc, int ccs) {
    const uint32_t d = sb + (uint32_t)(cr * 64 + ccs * 16);
    const size_t oa = (size_t)(m0 + cr) * 1024 + k0 + cc * 8;
    const size_t ob = (size_t)(n0 + cr) * 1024 + k0 + cc * 8;
    CP_ASYNC(d,         Ah + oa);
    CP_ASYNC(d + ST_AL, Al + oa);
    CP_ASYNC(d + ST_BH, Bh + ob);
    CP_ASYNC(d + ST_BL, Bl + ob);
}

template <int PASS>
__global__ __launch_bounds__(512, 1)
void k_mma(const __nv_bfloat16* __restrict__ Ah, const __nv_bfloat16* __restrict__ Al,
           const __nv_bfloat16* __restrict__ Bh, const __nv_bfloat16* __restrict__ Bl,
           const float* __restrict__ bqc, float* __restrict__ out) {
    extern __shared__ char sm[];
    const uint32_t sb = smem_u32(sm);
    const int tid = threadIdx.x;
    const int lane = tid & 31, wid = tid >> 5;
    const int wm = wid & 3, wn = wid >> 2;
    const int g = lane >> 2, tq = lane & 3;
    const int m0 = blockIdx.y * 128, n0 = blockIdx.x * 128;
    const int cr = tid >> 2, cc = tid & 3;
    const int ccs = cc ^ ((cr >> 1) & 3);
    const int lr = lane & 15, lc = lane >> 4;

    float4 acc[2][4];
#pragma unroll
    for (int i = 0; i < 2; ++i)
#pragma unroll
        for (int j = 0; j < 4; ++j) acc[i][j] = make_float4(0.f, 0.f, 0.f, 0.f);

    fill_stage(sb, Ah, Al, Bh, Bl, m0, n0, 0, cr, cc, ccs);  CP_COMMIT();
    fill_stage(sb + ST_SZ, Ah, Al, Bh, Bl, m0, n0, 32, cr, cc, ccs);  CP_COMMIT();

    for (int s = 0; s < 32; ++s) {
        if (s < 30)
            fill_stage(sb + (uint32_t)((s + 2) % 3) * ST_SZ, Ah, Al, Bh, Bl,
                       m0, n0, (s + 2) * 32, cr, cc, ccs);
        CP_COMMIT();
        CP_WAIT2();
        __syncthreads();

        const uint32_t buf = sb + (uint32_t)(s % 3) * ST_SZ;
#pragma unroll
        for (int kk = 0; kk < 2; ++kk) {
            uint32_t ah[2][4], al[2][4], bfh[2][4], bfl[2][4];
#pragma unroll
            for (int mt = 0; mt < 2; ++mt) {
                const int row = wm * 32 + mt * 16 + lr;
                const int ch = kk * 2 + lc;
                const uint32_t off = (uint32_t)(row * 64 + ((ch ^ ((row >> 1) & 3)) * 16));
                ldsm4(ah[mt], buf + off);
                ldsm4(al[mt], buf + ST_AL + off);
            }
#pragma unroll
            for (int nb = 0; nb < 2; ++nb) {
                const int row = wn * 32 + nb * 16 + lr;
                const int ch = kk * 2 + lc;
                const uint32_t off = (uint32_t)(row * 64 + ((ch ^ ((row >> 1) & 3)) * 16));
                ldsm4(bfh[nb], buf + ST_BH + off);
                ldsm4(bfl[nb], buf + ST_BL + off);
            }
#pragma unroll
            for (int mt = 0; mt < 2; ++mt)
#pragma unroll
                for (int nt = 0; nt < 4; ++nt) {
                    const int nb = nt >> 1, p = nt & 1;
                    mma16816(acc[mt][nt], ah[mt], bfh[nb][p], bfh[nb][p + 2]);
                    mma16816(acc[mt][nt], ah[mt], bfl[nb][p], bfl[nb][p + 2]);
                    mma16816(acc[mt][nt], al[mt], bfh[nb][p], bfh[nb][p + 2]);
                }
        }
        __syncthreads();
    }

    if (PASS == 1) {
        const float bq = bqc[0];
        float* s_cp = (float*)sm;  // [4][128] overlay
        float cs[4][2];
#pragma unroll
        for (int nt = 0; nt < 4; ++nt) { cs[nt][0] = 0.f; cs[nt][1] = 0.f; }
#pragma unroll
        for (int mt = 0; mt < 2; ++mt) {
            const int row = m0 + wm * 32 + mt * 16 + g;
            const float ct0 = g_cterm[row], ct1 = g_cterm[row + 8];
#pragma unroll
            for (int nt = 0; nt < 4; ++nt) {
                const int col = n0 + wn * 32 + nt * 8 + tq * 2;
                const float q0 = g_qterm[col] + bq, q1 = g_qterm[col + 1] + bq;
                const float4 c = acc[mt][nt];
                const float e00 = __expf(c.x + ct0 + q0), e01 = __expf(c.y + ct0 + q1);
                const float e10 = __expf(c.z + ct1 + q0), e11 = __expf(c.w + ct1 + q1);
                uint32_t h0, h1, l0, l1;
                split4(e00, e01, e10, e11, h0, h1, l0, l1);
                const size_t o0 = (size_t)row * 1024 + col;
                const size_t o1 = (size_t)(row + 8) * 1024 + col;
                *(uint32_t*)((uint16_t*)g_eh + o0) = h0;
                *(uint32_t*)((uint16_t*)g_el + o0) = l0;
                *(uint32_t*)((uint16_t*)g_eh + o1) = h1;
                *(uint32_t*)((uint16_t*)g_el + o1) = l1;
                cs[nt][0] += e00 + e10;
                cs[nt][1] += e01 + e11;
            }
        }
#pragma unroll
        for (int nt = 0; nt < 4; ++nt)
#pragma unroll
            for (int o = 4; o < 32; o <<= 1) {
                cs[nt][0] += __shfl_xor_sync(0xffffffffu, cs[nt][0], o);
                cs[nt][1] += __shfl_xor_sync(0xffffffffu, cs[nt][1], o);
            }
        if (g == 0) {
#pragma unroll
            for (int nt = 0; nt < 4; ++nt) {
                const int col = wn * 32 + nt * 8 + tq * 2;
                s_cp[wm * 128 + col] = cs[nt][0];
                s_cp[wm * 128 + col + 1] = cs[nt][1];
            }
        }
        __syncthreads();
        if (tid < 128) {
            const float v = s_cp[tid] + s_cp[128 + tid] + s_cp[256 + tid] + s_cp[384 + tid];
            g_colpart[blockIdx.y * 1024 + n0 + tid] = v;
        }
    } else {
#pragma unroll
        for (int mt = 0; mt < 2; ++mt) {
            const int row = m0 + wm * 32 + mt * 16 + g;
#pragma unroll
            for (int nt = 0; nt < 4; ++nt) {
                const int col = n0 + wn * 32 + nt * 8 + tq * 2;
                const float4 c = acc[mt][nt];
                *(float2*)(out + (size_t)row * 1024 + col) = make_float2(c.x, c.y);
                *(float2*)(out + (size_t)(row + 8) * 1024 + col) = make_float2(c.z, c.w);
            }
        }
    }
}

// ---------------- Z_q reduction -------------------------------------------------
__global__ void k_colfin() {
    const int q = blockIdx.x * 256 + threadIdx.x;
    float s = 0.f;
#pragma unroll
    for (int i = 0; i < 64; ++i) s += g_colpart[i * 1024 + q];
    g_rz[q] = 1.f / s;
}

// ---------------- c2q softmax ---------------------------------------------------
__global__ void k_c2q() {
    const int t = threadIdx.x;
    const int lane = t & 31, wid = t >> 5;
    __shared__ float sred[32];
    __shared__ float sbc[2];
    float m = -1e30f;
    for (int c = t; c < C_LEN; c += 1024) m = fmaxf(m, g_bmax[c]);
#pragma unroll
    for (int o = 16; o; o >>= 1) m = fmaxf(m, __shfl_xor_sync(0xffffffffu, m, o));
    if (lane == 0) sred[wid] = m;
    __syncthreads();
    if (t < 32) {
        float v = sred[t];
#pragma unroll
        for (int o = 16; o; o >>= 1) v = fmaxf(v, __shfl_xor_sync(0xffffffffu, v, o));
        if (t == 0) sbc[0] = v;
    }
    __syncthreads();
    const float mm = sbc[0];
    float z = 0.f;
    for (int c = t; c < C_LEN; c += 1024) z += expf(g_bmax[c] - mm);
#pragma unroll
    for (int o = 16; o; o >>= 1) z += __shfl_xor_sync(0xffffffffu, z, o);
    __syncthreads();
    if (lane == 0) sred[wid] = z;
    __syncthreads();
    if (t < 32) {
        float v = sred[t];
#pragma unroll
        for (int o = 16; o; o >>= 1) v += __shfl_xor_sync(0xffffffffu, v, o);
        if (t == 0) sbc[1] = v;
    }
    __syncthreads();
    const float rz = 1.f / sbc[1];
    for (int c = t; c < C_LEN; c += 1024) g_w[c] = expf(g_bmax[c] - mm) * rz;
}

// ---------------- weighted column sum of H ---------------------------------------
__global__ void k_hpart(const float* __restrict__ H) {
    const int chunk = blockIdx.x, t = threadIdx.x;
    float a0 = 0.f, a1 = 0.f, a2 = 0.f, a3 = 0.f;
    const int c0 = chunk * 128;
    for (int c = c0; c < c0 + 128; ++c) {
        const float wv = g_w[c];
        const float* hr = H + (size_t)c * 1024;
        a0 = fmaf(wv, hr[t], a0);
        a1 = fmaf(wv, hr[t + 256], a1);
        a2 = fmaf(wv, hr[t + 512], a2);
        a3 = fmaf(wv, hr[t + 768], a3);
    }
    g_hpart[chunk][t] = a0;
    g_hpart[chunk][t + 256] = a1;
    g_hpart[chunk][t + 512] = a2;
    g_hpart[chunk][t + 768] = a3;
}

__global__ void k_hred() {
    const int d = blockIdx.x * 256 + threadIdx.x;
    float s = 0.f;
#pragma unroll
    for (int i = 0; i < 64; ++i) s += g_hpart[i][d];
    g_hrow[d] = s;
}

__global__ void k_bcast(float* __restrict__ out) {
    const float4 v = ((const float4*)g_hrow)[threadIdx.x];
    ((float4*)(out + (size_t)C_LEN * D_DIM))[blockIdx.x * 256 + threadIdx.x] = v;
}

// ---------------- launch ----------------------------------------------------------
extern "C" void kernel_launch(void* const* d_in, const int* in_sizes, int n_in,
                              void* d_out, int out_size) {
    const float* H   = (const float*)d_in[0];
    const float* U   = (const float*)d_in[1];
    const float* wq  = (const float*)d_in[2];
    const float* bq  = (const float*)d_in[3];
    const float* wc  = (const float*)d_in[4];
    const float* bc  = (const float*)d_in[5];
    const float* wqc = (const float*)d_in[6];
    const float* bqc = (const float*)d_in[7];
    float* out = (float*)d_out;

    static bool s_attr = false;
    if (!s_attr) {
        cudaFuncSetAttribute(k_mma<1>, cudaFuncAttributeMaxDynamicSharedMemorySize, 3 * ST_SZ);
        cudaFuncSetAttribute(k_mma<2>, cudaFuncAttributeMaxDynamicSharedMemorySize, 3 * ST_SZ);
        s_attr = true;
    }

    // device-global pointers resolved host-side via symbol addresses is not allowed;
    // instead pass via kernel args using the device symbols directly in device code.
    k_qterm<<<Q_LEN, 256>>>(U, wq, bq);
    k_rowstat<<<C_LEN, 256>>>(H, wc, bc);
    k_prep_h<<<C_LEN * 4 / 4, 256>>>(H);
    k_prep_uw<<<Q_LEN, 256>>>(U, wqc);
    {
        // obtain device symbol addresses (host API, graph-capture safe; no allocation)
        void *hh, *hl, *b1h, *b1l;
        cudaGetSymbolAddress(&hh, g_Hh);
        cudaGetSymbolAddress(&hl, g_Hl);
        cudaGetSymbolAddress(&b1h, g_B1h);
        cudaGetSymbolAddress(&b1l, g_B1l);
        k_mma<1><<<dim3(8, 64), 512, 3 * ST_SZ>>>((const __nv_bfloat16*)hh, (const __nv_bfloat16*)hl,
                                                  (const __nv_bfloat16*)b1h, (const __nv_bfloat16*)b1l,
                                                  bqc, nullptr);
    }
    k_colfin<<<4, 256>>>();
    k_prep_ut<<<dim3(32, 32), 256>>>(U);
    {
        void *eh, *el, *b2h, *b2l;
        cudaGetSymbolAddress(&eh, g_eh);
        cudaGetSymbolAddress(&el, g_el);
        cudaGetSymbolAddress(&b2h, g_B2h);
        cudaGetSymbolAddress(&b2l, g_B2l);
        k_mma<2><<<dim3(8, 64), 512, 3 * ST_SZ>>>((const __nv_bfloat16*)eh, (const __nv_bfloat16*)el,
                                                  (const __nv_bfloat16*)b2h, (const __nv_bfloat16*)b2l,
                                                  bqc, out);
    }
    k_c2q<<<1, 1024>>>();
    k_hpart<<<64, 256>>>(H);
    k_hred<<<4, 256>>>();
    k_bcast<<<C_LEN, 256>>>(out);
}

// round 6
// speedup vs baseline: 2.0684x; 1.0157x over previous
#include <cuda_runtime.h>
#include <cuda_bf16.h>
#include <cstdint>
#include <math.h>

#define C_LEN 8192
#define Q_LEN 1024
#define D_DIM 1024

// ---------------- scratch (device globals) -----------------------------------
__device__ __align__(16) __nv_bfloat16 g_Hh[C_LEN * D_DIM];
__device__ __align__(16) __nv_bfloat16 g_Hl[C_LEN * D_DIM];
__device__ __align__(16) __nv_bfloat16 g_B1h[Q_LEN * D_DIM];
__device__ __align__(16) __nv_bfloat16 g_B1l[Q_LEN * D_DIM];
__device__ __align__(16) __nv_bfloat16 g_B2h[D_DIM * Q_LEN];
__device__ __align__(16) __nv_bfloat16 g_B2l[D_DIM * Q_LEN];
__device__ __align__(16) __nv_bfloat16 g_eh[C_LEN * Q_LEN];
__device__ __align__(16) __nv_bfloat16 g_el[C_LEN * Q_LEN];
__device__ __align__(16) float g_qterm[Q_LEN];
__device__ __align__(16) float g_cterm[C_LEN];
__device__ __align__(16) float g_bmax[C_LEN];
__device__ __align__(16) float g_colpart[64 * Q_LEN];
__device__ __align__(16) float g_rz[Q_LEN];
__device__ __align__(16) float g_w[C_LEN];
__device__ __align__(16) float g_hpart[64][D_DIM];
__device__ __align__(16) float g_hrow[D_DIM];

// ---------------- helpers -----------------------------------------------------
__device__ __forceinline__ uint32_t smem_u32(const void* p) {
    uint32_t a;
    asm("{ .reg .u64 t; cvta.to.shared.u64 t, %1; cvt.u32.u64 %0, t; }" : "=r"(a) : "l"(p));
    return a;
}
__device__ __forceinline__ uint32_t pack_lo_bf16x2(float l0, float l1) {
    uint32_t r;
    asm("cvt.rn.bf16x2.f32 %0, %1, %2;" : "=r"(r) : "f"(l1), "f"(l0));
    return r;
}
__device__ __forceinline__ void split4(float x, float y, float z, float w,
                                       uint32_t& h0, uint32_t& h1,
                                       uint32_t& l0, uint32_t& l1) {
    uint32_t bx = __float_as_uint(x), by = __float_as_uint(y);
    uint32_t bz = __float_as_uint(z), bw = __float_as_uint(w);
    h0 = __byte_perm(bx, by, 0x7632);
    h1 = __byte_perm(bz, bw, 0x7632);
    l0 = pack_lo_bf16x2(x - __uint_as_float(bx & 0xffff0000u),
                        y - __uint_as_float(by & 0xffff0000u));
    l1 = pack_lo_bf16x2(z - __uint_as_float(bz & 0xffff0000u),
                        w - __uint_as_float(bw & 0xffff0000u));
}
__device__ __forceinline__ void mma16816(float4& c, const uint32_t a[4],
                                         uint32_t b0, uint32_t b1) {
    asm volatile(
        "mma.sync.aligned.m16n8k16.row.col.f32.bf16.bf16.f32 "
        "{%0,%1,%2,%3}, {%4,%5,%6,%7}, {%8,%9}, {%0,%1,%2,%3};"
        : "+f"(c.x), "+f"(c.y), "+f"(c.z), "+f"(c.w)
        : "r"(a[0]), "r"(a[1]), "r"(a[2]), "r"(a[3]), "r"(b0), "r"(b1));
}
__device__ __forceinline__ void ldsm4(uint32_t d[4], uint32_t a) {
    asm volatile("ldmatrix.sync.aligned.m8n8.x4.shared.b16 {%0,%1,%2,%3}, [%4];"
                 : "=r"(d[0]), "=r"(d[1]), "=r"(d[2]), "=r"(d[3]) : "r"(a));
}
#define CP_ASYNC(d, s) asm volatile("cp.async.ca.shared.global [%0], [%1], 16;" :: "r"(d), "l"(s) : "memory")
#define CP_COMMIT()    asm volatile("cp.async.commit_group;" ::: "memory")
#define CP_WAIT3()     asm volatile("cp.async.wait_group 3;" ::: "memory")

// ---------------- fused stats: rowstat (blocks 0..8191) + qterm (8192..9215) --
__global__ void k_stats(const float* __restrict__ H, const float* __restrict__ U,
                        const float* __restrict__ wq, const float* __restrict__ bq,
                        const float* __restrict__ wc, const float* __restrict__ bc) {
    const int t = threadIdx.x;
    __shared__ float sp[8], sm2[8];
    if (blockIdx.x < C_LEN) {
        const int c = blockIdx.x;
        float4 h = ((const float4*)H)[c * 256 + t];
        float4 w = ((const float4*)wc)[t];
        float p = h.x * w.x + h.y * w.y + h.z * w.z + h.w * w.w;
        float m = fmaxf(fmaxf(h.x, h.y), fmaxf(h.z, h.w));
#pragma unroll
        for (int o = 16; o; o >>= 1) {
            p += __shfl_down_sync(0xffffffffu, p, o);
            m = fmaxf(m, __shfl_down_sync(0xffffffffu, m, o));
        }
        if ((t & 31) == 0) { sp[t >> 5] = p; sm2[t >> 5] = m; }
        __syncthreads();
        if (t == 0) {
            float pp = sp[0], mm = sm2[0];
#pragma unroll
            for (int i = 1; i < 8; ++i) { pp += sp[i]; mm = fmaxf(mm, sm2[i]); }
            g_cterm[c] = pp + bc[0];
            g_bmax[c] = mm;
        }
    } else {
        const int n = blockIdx.x - C_LEN;
        float4 u = ((const float4*)U)[n * 256 + t];
        float4 w = ((const float4*)wq)[t];
        float p = u.x * w.x + u.y * w.y + u.z * w.z + u.w * w.w;
#pragma unroll
        for (int o = 16; o; o >>= 1) p += __shfl_down_sync(0xffffffffu, p, o);
        if ((t & 31) == 0) sp[t >> 5] = p;
        __syncthreads();
        if (t == 0) {
            float s = sp[0];
#pragma unroll
            for (int i = 1; i < 8; ++i) s += sp[i];
            g_qterm[n] = s + bq[0];
        }
    }
}

// ---------------- prep: split H  (8192 blocks x 256 thr x 4 elts = 8.39M) ----
__global__ void k_prep_h(const float* __restrict__ H) {
    const int i = (blockIdx.x * 256 + threadIdx.x) * 4;
    float4 a = *(const float4*)(H + i);
    uint32_t h0, h1, l0, l1;
    split4(a.x, a.y, a.z, a.w, h0, h1, l0, l1);
    *(uint2*)((uint16_t*)g_Hh + i) = make_uint2(h0, h1);
    *(uint2*)((uint16_t*)g_Hl + i) = make_uint2(l0, l1);
}

// ---------------- prep: split (U * wqc) ----------------------------------------
__global__ void k_prep_uw(const float* __restrict__ U, const float* __restrict__ wqc) {
    const int q = blockIdx.x, t = threadIdx.x;
    const int i = q * 1024 + t * 4;
    float4 a = *(const float4*)(U + i);
    float4 w = ((const float4*)wqc)[t];
    a.x *= w.x; a.y *= w.y; a.z *= w.z; a.w *= w.w;
    uint32_t h0, h1, l0, l1;
    split4(a.x, a.y, a.z, a.w, h0, h1, l0, l1);
    *(uint2*)((uint16_t*)g_B1h + i) = make_uint2(h0, h1);
    *(uint2*)((uint16_t*)g_B1l + i) = make_uint2(l0, l1);
}

// ---------------- prep: transpose+split (U * rz)^T -----------------------------
__global__ void k_prep_ut(const float* __restrict__ U) {
    __shared__ float t[32][33];
    const int tx = threadIdx.x & 31, ty = threadIdx.x >> 5;
    const int d0 = blockIdx.x * 32, q0 = blockIdx.y * 32;
#pragma unroll
    for (int i = 0; i < 4; ++i)
        t[ty + 8 * i][tx] = U[(size_t)(q0 + ty + 8 * i) * 1024 + d0 + tx];
    __syncthreads();
#pragma unroll
    for (int i = 0; i < 4; ++i) {
        const int d = d0 + ty + 8 * i;
        const int q = q0 + tx;
        const float v = t[tx][ty + 8 * i] * g_rz[q];
        const uint32_t b = __float_as_uint(v);
        ((uint16_t*)g_B2h)[(size_t)d * 1024 + q] = (uint16_t)(b >> 16);
        const float l = v - __uint_as_float(b & 0xffff0000u);
        ((__nv_bfloat16*)g_B2l)[(size_t)d * 1024 + q] = __float2bfloat16(l);
    }
}

// ---------------- GEMM: 5-stage cp.async, K=16/stage, 8 warps 64x32 -----------
// stage = Ah(4K) | Al(4K) | Bh(4K) | Bl(4K) = 16KB, 5 stages = 80KB
#define TS    16384u
#define O_AL  4096u
#define O_BH  8192u
#define O_BL  12288u
#define NSTG  5

__device__ __forceinline__ void fill_stage(uint32_t sbuf,
                                           const __nv_bfloat16* Ah, const __nv_bfloat16* Al,
                                           const __nv_bfloat16* Bh, const __nv_bfloat16* Bl,
                                           int m0, int n0, int k0, int t) {
    const int row = t >> 1, ch = t & 1;
    const int chs = ch ^ ((row >> 2) & 1);
    const uint32_t d = sbuf + (uint32_t)(row * 32 + chs * 16);
    const size_t oa = (size_t)(m0 + row) * 1024 + k0 + ch * 8;
    const size_t ob = (size_t)(n0 + row) * 1024 + k0 + ch * 8;
    CP_ASYNC(d,        Ah + oa);
    CP_ASYNC(d + O_AL, Al + oa);
    CP_ASYNC(d + O_BH, Bh + ob);
    CP_ASYNC(d + O_BL, Bl + ob);
}

template <int PASS>
__global__ __launch_bounds__(256, 1)
void k_mma(const __nv_bfloat16* __restrict__ Ah, const __nv_bfloat16* __restrict__ Al,
           const __nv_bfloat16* __restrict__ Bh, const __nv_bfloat16* __restrict__ Bl,
           const float* __restrict__ bqc, float* __restrict__ out) {
    extern __shared__ char sm[];
    const uint32_t sb = smem_u32(sm);
    const int tid = threadIdx.x;
    const int lane = tid & 31, wid = tid >> 5;
    const int wm = wid & 1, wn = wid >> 1;           // 2 x 4 warps, warp tile 64x32
    const int g = lane >> 2, tq = lane & 3;
    const int m0 = blockIdx.y * 128, n0 = blockIdx.x * 128;
    const int lr = lane & 15, lc = lane >> 4;

    float4 acc[4][4];
#pragma unroll
    for (int i = 0; i < 4; ++i)
#pragma unroll
        for (int j = 0; j < 4; ++j) acc[i][j] = make_float4(0.f, 0.f, 0.f, 0.f);

#pragma unroll
    for (int s = 0; s < 4; ++s) {
        fill_stage(sb + s * TS, Ah, Al, Bh, Bl, m0, n0, s * 16, tid);
        CP_COMMIT();
    }

    for (int s = 0; s < 64; ++s) {
        CP_WAIT3();
        __syncthreads();
        const uint32_t buf = sb + (uint32_t)(s % NSTG) * TS;

        uint32_t ah[4][4], al[4][4], bh[2][4], bl[2][4];
#pragma unroll
        for (int mt = 0; mt < 4; ++mt) {
            const int row = wm * 64 + mt * 16 + lr;
            const uint32_t off = (uint32_t)(row * 32 + ((lc ^ ((row >> 2) & 1)) * 16));
            ldsm4(ah[mt], buf + off);
            ldsm4(al[mt], buf + O_AL + off);
        }
#pragma unroll
        for (int nb = 0; nb < 2; ++nb) {
            const int row = wn * 32 + nb * 16 + lr;
            const uint32_t off = (uint32_t)(row * 32 + ((lc ^ ((row >> 2) & 1)) * 16));
            ldsm4(bh[nb], buf + O_BH + off);
            ldsm4(bl[nb], buf + O_BL + off);
        }
#pragma unroll
        for (int mt = 0; mt < 4; ++mt)
#pragma unroll
            for (int nt = 0; nt < 4; ++nt) {
                const int nb = nt >> 1, p = nt & 1;
                mma16816(acc[mt][nt], ah[mt], bh[nb][p], bh[nb][p + 2]);
                mma16816(acc[mt][nt], ah[mt], bl[nb][p], bl[nb][p + 2]);
                mma16816(acc[mt][nt], al[mt], bh[nb][p], bh[nb][p + 2]);
            }

        if (s < 60)
            fill_stage(sb + (uint32_t)((s + 4) % NSTG) * TS, Ah, Al, Bh, Bl,
                       m0, n0, (s + 4) * 16, tid);
        CP_COMMIT();
    }
    __syncthreads();

    if (PASS == 1) {
        const float bq = bqc[0];
        float* s_cp = (float*)sm;  // [2][128] overlay
        float cs[4][2];
#pragma unroll
        for (int nt = 0; nt < 4; ++nt) { cs[nt][0] = 0.f; cs[nt][1] = 0.f; }
#pragma unroll
        for (int mt = 0; mt < 4; ++mt) {
            const int row = m0 + wm * 64 + mt * 16 + g;
            const float ct0 = g_cterm[row], ct1 = g_cterm[row + 8];
#pragma unroll
            for (int nt = 0; nt < 4; ++nt) {
                const int col = n0 + wn * 32 + nt * 8 + tq * 2;
                const float q0 = g_qterm[col] + bq, q1 = g_qterm[col + 1] + bq;
                const float4 c = acc[mt][nt];
                const float e00 = __expf(c.x + ct0 + q0), e01 = __expf(c.y + ct0 + q1);
                const float e10 = __expf(c.z + ct1 + q0), e11 = __expf(c.w + ct1 + q1);
                uint32_t h0, h1, l0, l1;
                split4(e00, e01, e10, e11, h0, h1, l0, l1);
                const size_t o0 = (size_t)row * 1024 + col;
                const size_t o1 = (size_t)(row + 8) * 1024 + col;
                *(uint32_t*)((uint16_t*)g_eh + o0) = h0;
                *(uint32_t*)((uint16_t*)g_el + o0) = l0;
                *(uint32_t*)((uint16_t*)g_eh + o1) = h1;
                *(uint32_t*)((uint16_t*)g_el + o1) = l1;
                cs[nt][0] += e00 + e10;
                cs[nt][1] += e01 + e11;
            }
        }
#pragma unroll
        for (int nt = 0; nt < 4; ++nt)
#pragma unroll
            for (int o = 4; o < 32; o <<= 1) {
                cs[nt][0] += __shfl_xor_sync(0xffffffffu, cs[nt][0], o);
                cs[nt][1] += __shfl_xor_sync(0xffffffffu, cs[nt][1], o);
            }
        if (g == 0) {
#pragma unroll
            for (int nt = 0; nt < 4; ++nt) {
                const int col = wn * 32 + nt * 8 + tq * 2;
                s_cp[wm * 128 + col] = cs[nt][0];
                s_cp[wm * 128 + col + 1] = cs[nt][1];
            }
        }
        __syncthreads();
        if (tid < 128) {
            const float v = s_cp[tid] + s_cp[128 + tid];
            g_colpart[blockIdx.y * 1024 + n0 + tid] = v;
        }
    } else {
#pragma unroll
        for (int mt = 0; mt < 4; ++mt) {
            const int row = m0 + wm * 64 + mt * 16 + g;
#pragma unroll
            for (int nt = 0; nt < 4; ++nt) {
                const int col = n0 + wn * 32 + nt * 8 + tq * 2;
                const float4 c = acc[mt][nt];
                *(float2*)(out + (size_t)row * 1024 + col) = make_float2(c.x, c.y);
                *(float2*)(out + (size_t)(row + 8) * 1024 + col) = make_float2(c.z, c.w);
            }
        }
    }
}

// ---------------- Z_q reduction -------------------------------------------------
__global__ void k_colfin() {
    const int q = blockIdx.x * 256 + threadIdx.x;
    float s = 0.f;
#pragma unroll
    for (int i = 0; i < 64; ++i) s += g_colpart[i * 1024 + q];
    g_rz[q] = 1.f / s;
}

// ---------------- c2q softmax ---------------------------------------------------
__global__ void k_c2q() {
    const int t = threadIdx.x;
    const int lane = t & 31, wid = t >> 5;
    __shared__ float sred[32];
    __shared__ float sbc[2];
    float m = -1e30f;
    for (int c = t; c < C_LEN; c += 1024) m = fmaxf(m, g_bmax[c]);
#pragma unroll
    for (int o = 16; o; o >>= 1) m = fmaxf(m, __shfl_xor_sync(0xffffffffu, m, o));
    if (lane == 0) sred[wid] = m;
    __syncthreads();
    if (t < 32) {
        float v = sred[t];
#pragma unroll
        for (int o = 16; o; o >>= 1) v = fmaxf(v, __shfl_xor_sync(0xffffffffu, v, o));
        if (t == 0) sbc[0] = v;
    }
    __syncthreads();
    const float mm = sbc[0];
    float z = 0.f;
    for (int c = t; c < C_LEN; c += 1024) z += expf(g_bmax[c] - mm);
#pragma unroll
    for (int o = 16; o; o >>= 1) z += __shfl_xor_sync(0xffffffffu, z, o);
    __syncthreads();
    if (lane == 0) sred[wid] = z;
    __syncthreads();
    if (t < 32) {
        float v = sred[t];
#pragma unroll
        for (int o = 16; o; o >>= 1) v += __shfl_xor_sync(0xffffffffu, v, o);
        if (t == 0) sbc[1] = v;
    }
    __syncthreads();
    const float rz = 1.f / sbc[1];
    for (int c = t; c < C_LEN; c += 1024) g_w[c] = expf(g_bmax[c] - mm) * rz;
}

// ---------------- weighted column sum of H ---------------------------------------
__global__ void k_hpart(const float* __restrict__ H) {
    const int chunk = blockIdx.x, t = threadIdx.x;
    float a0 = 0.f, a1 = 0.f, a2 = 0.f, a3 = 0.f;
    const int c0 = chunk * 128;
    for (int c = c0; c < c0 + 128; ++c) {
        const float wv = g_w[c];
        const float* hr = H + (size_t)c * 1024;
        a0 = fmaf(wv, hr[t], a0);
        a1 = fmaf(wv, hr[t + 256], a1);
        a2 = fmaf(wv, hr[t + 512], a2);
        a3 = fmaf(wv, hr[t + 768], a3);
    }
    g_hpart[chunk][t] = a0;
    g_hpart[chunk][t + 256] = a1;
    g_hpart[chunk][t + 512] = a2;
    g_hpart[chunk][t + 768] = a3;
}

__global__ void k_hred() {
    const int d = blockIdx.x * 256 + threadIdx.x;
    float s = 0.f;
#pragma unroll
    for (int i = 0; i < 64; ++i) s += g_hpart[i][d];
    g_hrow[d] = s;
}

__global__ void k_bcast(float* __restrict__ out) {
    const float4 v = ((const float4*)g_hrow)[threadIdx.x];
    ((float4*)(out + (size_t)C_LEN * D_DIM))[blockIdx.x * 256 + threadIdx.x] = v;
}

// ---------------- launch ----------------------------------------------------------
extern "C" void kernel_launch(void* const* d_in, const int* in_sizes, int n_in,
                              void* d_out, int out_size) {
    const float* H   = (const float*)d_in[0];
    const float* U   = (const float*)d_in[1];
    const float* wq  = (const float*)d_in[2];
    const float* bq  = (const float*)d_in[3];
    const float* wc  = (const float*)d_in[4];
    const float* bc  = (const float*)d_in[5];
    const float* wqc = (const float*)d_in[6];
    const float* bqc = (const float*)d_in[7];
    float* out = (float*)d_out;

    static bool s_attr = false;
    if (!s_attr) {
        cudaFuncSetAttribute(k_mma<1>, cudaFuncAttributeMaxDynamicSharedMemorySize, NSTG * TS);
        cudaFuncSetAttribute(k_mma<2>, cudaFuncAttributeMaxDynamicSharedMemorySize, NSTG * TS);
        s_attr = true;
    }

    void *hh, *hl, *b1h, *b1l, *eh, *el, *b2h, *b2l;
    cudaGetSymbolAddress(&hh, g_Hh);
    cudaGetSymbolAddress(&hl, g_Hl);
    cudaGetSymbolAddress(&b1h, g_B1h);
    cudaGetSymbolAddress(&b1l, g_B1l);
    cudaGetSymbolAddress(&eh, g_eh);
    cudaGetSymbolAddress(&el, g_el);
    cudaGetSymbolAddress(&b2h, g_B2h);
    cudaGetSymbolAddress(&b2l, g_B2l);

    k_stats<<<C_LEN + Q_LEN, 256>>>(H, U, wq, bq, wc, bc);
    k_prep_h<<<C_LEN * D_DIM / 1024, 256>>>(H);   // 8192 blocks (R5 bug: was 4x too many)
    k_prep_uw<<<Q_LEN, 256>>>(U, wqc);
    k_mma<1><<<dim3(8, 64), 256, NSTG * TS>>>((const __nv_bfloat16*)hh, (const __nv_bfloat16*)hl,
                                              (const __nv_bfloat16*)b1h, (const __nv_bfloat16*)b1l,
                                              bqc, nullptr);
    k_colfin<<<4, 256>>>();
    k_prep_ut<<<dim3(32, 32), 256>>>(U);
    k_mma<2><<<dim3(8, 64), 256, NSTG * TS>>>((const __nv_bfloat16*)eh, (const __nv_bfloat16*)el,
                                              (const __nv_bfloat16*)b2h, (const __nv_bfloat16*)b2l,
                                              bqc, out);
    k_c2q<<<1, 1024>>>();
    k_hpart<<<64, 256>>>(H);
    k_hred<<<4, 256>>>();
    k_bcast<<<C_LEN, 256>>>(out);
}

// round 7
// speedup vs baseline: 2.1493x; 1.0391x over previous
#include <cuda_runtime.h>
#include <cuda_bf16.h>
#include <cstdint>
#include <math.h>

#define C_LEN 8192
#define Q_LEN 1024
#define D_DIM 1024

// ---------------- scratch (device globals) -----------------------------------
__device__ __align__(16) __nv_bfloat16 g_Hh[C_LEN * D_DIM];
__device__ __align__(16) __nv_bfloat16 g_Hl[C_LEN * D_DIM];
__device__ __align__(16) __nv_bfloat16 g_B1h[Q_LEN * D_DIM];
__device__ __align__(16) __nv_bfloat16 g_B1l[Q_LEN * D_DIM];
__device__ __align__(16) __nv_bfloat16 g_B2h[D_DIM * Q_LEN];
__device__ __align__(16) __nv_bfloat16 g_B2l[D_DIM * Q_LEN];
__device__ __align__(16) __nv_bfloat16 g_eh[C_LEN * Q_LEN];
__device__ __align__(16) __nv_bfloat16 g_el[C_LEN * Q_LEN];
__device__ __align__(16) float g_qterm[Q_LEN];
__device__ __align__(16) float g_cterm[C_LEN];
__device__ __align__(16) float g_bmax[C_LEN];
__device__ __align__(16) float g_colpart[64 * Q_LEN];
__device__ __align__(16) float g_rz[Q_LEN];
__device__ __align__(16) float g_w[C_LEN];
__device__ __align__(16) float g_hpart[64][D_DIM];
__device__ __align__(16) float g_hrow[D_DIM];

// ---------------- helpers -----------------------------------------------------
__device__ __forceinline__ uint32_t smem_u32(const void* p) {
    uint32_t a;
    asm("{ .reg .u64 t; cvta.to.shared.u64 t, %1; cvt.u32.u64 %0, t; }" : "=r"(a) : "l"(p));
    return a;
}
__device__ __forceinline__ uint32_t pack_lo_bf16x2(float l0, float l1) {
    uint32_t r;
    asm("cvt.rn.bf16x2.f32 %0, %1, %2;" : "=r"(r) : "f"(l1), "f"(l0));
    return r;
}
__device__ __forceinline__ void split4(float x, float y, float z, float w,
                                       uint32_t& h0, uint32_t& h1,
                                       uint32_t& l0, uint32_t& l1) {
    uint32_t bx = __float_as_uint(x), by = __float_as_uint(y);
    uint32_t bz = __float_as_uint(z), bw = __float_as_uint(w);
    h0 = __byte_perm(bx, by, 0x7632);
    h1 = __byte_perm(bz, bw, 0x7632);
    l0 = pack_lo_bf16x2(x - __uint_as_float(bx & 0xffff0000u),
                        y - __uint_as_float(by & 0xffff0000u));
    l1 = pack_lo_bf16x2(z - __uint_as_float(bz & 0xffff0000u),
                        w - __uint_as_float(bw & 0xffff0000u));
}
__device__ __forceinline__ void mma16816(float4& c, const uint32_t a[4],
                                         uint32_t b0, uint32_t b1) {
    asm volatile(
        "mma.sync.aligned.m16n8k16.row.col.f32.bf16.bf16.f32 "
        "{%0,%1,%2,%3}, {%4,%5,%6,%7}, {%8,%9}, {%0,%1,%2,%3};"
        : "+f"(c.x), "+f"(c.y), "+f"(c.z), "+f"(c.w)
        : "r"(a[0]), "r"(a[1]), "r"(a[2]), "r"(a[3]), "r"(b0), "r"(b1));
}
__device__ __forceinline__ void ldsm4(uint32_t d[4], uint32_t a) {
    asm volatile("ldmatrix.sync.aligned.m8n8.x4.shared.b16 {%0,%1,%2,%3}, [%4];"
                 : "=r"(d[0]), "=r"(d[1]), "=r"(d[2]), "=r"(d[3]) : "r"(a));
}
#define CP_ASYNC(d, s) asm volatile("cp.async.ca.shared.global [%0], [%1], 16;" :: "r"(d), "l"(s) : "memory")
#define CP_COMMIT()    asm volatile("cp.async.commit_group;" ::: "memory")
#define CP_WAIT2()     asm volatile("cp.async.wait_group 2;" ::: "memory")

// ---------------- fused stats: rowstat (blocks 0..8191) + qterm (8192..9215) --
__global__ void k_stats(const float* __restrict__ H, const float* __restrict__ U,
                        const float* __restrict__ wq, const float* __restrict__ bq,
                        const float* __restrict__ wc, const float* __restrict__ bc) {
    const int t = threadIdx.x;
    __shared__ float sp[8], sm2[8];
    if (blockIdx.x < C_LEN) {
        const int c = blockIdx.x;
        float4 h = ((const float4*)H)[c * 256 + t];
        float4 w = ((const float4*)wc)[t];
        float p = h.x * w.x + h.y * w.y + h.z * w.z + h.w * w.w;
        float m = fmaxf(fmaxf(h.x, h.y), fmaxf(h.z, h.w));
#pragma unroll
        for (int o = 16; o; o >>= 1) {
            p += __shfl_down_sync(0xffffffffu, p, o);
            m = fmaxf(m, __shfl_down_sync(0xffffffffu, m, o));
        }
        if ((t & 31) == 0) { sp[t >> 5] = p; sm2[t >> 5] = m; }
        __syncthreads();
        if (t == 0) {
            float pp = sp[0], mm = sm2[0];
#pragma unroll
            for (int i = 1; i < 8; ++i) { pp += sp[i]; mm = fmaxf(mm, sm2[i]); }
            g_cterm[c] = pp + bc[0];
            g_bmax[c] = mm;
        }
    } else {
        const int n = blockIdx.x - C_LEN;
        float4 u = ((const float4*)U)[n * 256 + t];
        float4 w = ((const float4*)wq)[t];
        float p = u.x * w.x + u.y * w.y + u.z * w.z + u.w * w.w;
#pragma unroll
        for (int o = 16; o; o >>= 1) p += __shfl_down_sync(0xffffffffu, p, o);
        if ((t & 31) == 0) sp[t >> 5] = p;
        __syncthreads();
        if (t == 0) {
            float s = sp[0];
#pragma unroll
            for (int i = 1; i < 8; ++i) s += sp[i];
            g_qterm[n] = s + bq[0];
        }
    }
}

// ---------------- prep: split H  (8192 blocks x 256 thr x 4 elts = 8.39M) ----
__global__ void k_prep_h(const float* __restrict__ H) {
    const int i = (blockIdx.x * 256 + threadIdx.x) * 4;
    float4 a = *(const float4*)(H + i);
    uint32_t h0, h1, l0, l1;
    split4(a.x, a.y, a.z, a.w, h0, h1, l0, l1);
    *(uint2*)((uint16_t*)g_Hh + i) = make_uint2(h0, h1);
    *(uint2*)((uint16_t*)g_Hl + i) = make_uint2(l0, l1);
}

// ---------------- prep: split (U * wqc) ----------------------------------------
__global__ void k_prep_uw(const float* __restrict__ U, const float* __restrict__ wqc) {
    const int q = blockIdx.x, t = threadIdx.x;
    const int i = q * 1024 + t * 4;
    float4 a = *(const float4*)(U + i);
    float4 w = ((const float4*)wqc)[t];
    a.x *= w.x; a.y *= w.y; a.z *= w.z; a.w *= w.w;
    uint32_t h0, h1, l0, l1;
    split4(a.x, a.y, a.z, a.w, h0, h1, l0, l1);
    *(uint2*)((uint16_t*)g_B1h + i) = make_uint2(h0, h1);
    *(uint2*)((uint16_t*)g_B1l + i) = make_uint2(l0, l1);
}

// ---------------- prep: transpose+split (U * rz)^T -----------------------------
__global__ void k_prep_ut(const float* __restrict__ U) {
    __shared__ float t[32][33];
    const int tx = threadIdx.x & 31, ty = threadIdx.x >> 5;
    const int d0 = blockIdx.x * 32, q0 = blockIdx.y * 32;
#pragma unroll
    for (int i = 0; i < 4; ++i)
        t[ty + 8 * i][tx] = U[(size_t)(q0 + ty + 8 * i) * 1024 + d0 + tx];
    __syncthreads();
#pragma unroll
    for (int i = 0; i < 4; ++i) {
        const int d = d0 + ty + 8 * i;
        const int q = q0 + tx;
        const float v = t[tx][ty + 8 * i] * g_rz[q];
        const uint32_t b = __float_as_uint(v);
        ((uint16_t*)g_B2h)[(size_t)d * 1024 + q] = (uint16_t)(b >> 16);
        const float l = v - __uint_as_float(b & 0xffff0000u);
        ((__nv_bfloat16*)g_B2l)[(size_t)d * 1024 + q] = __float2bfloat16(l);
    }
}

// ---------------- GEMM: 4-stage cp.async, K=16/stage, 8 warps 64x32, 2 CTA/SM --
// stage = Ah(4K) | Al(4K) | Bh(4K) | Bl(4K) = 16KB, 4 stages = 64KB
#define TS    16384u
#define O_AL  4096u
#define O_BH  8192u
#define O_BL  12288u
#define NSTG  4

__device__ __forceinline__ void fill_stage(uint32_t sbuf,
                                           const __nv_bfloat16* Ah, const __nv_bfloat16* Al,
                                           const __nv_bfloat16* Bh, const __nv_bfloat16* Bl,
                                           int m0, int n0, int k0, int t) {
    const int row = t >> 1, ch = t & 1;
    const int chs = ch ^ ((row >> 2) & 1);
    const uint32_t d = sbuf + (uint32_t)(row * 32 + chs * 16);
    const size_t oa = (size_t)(m0 + row) * 1024 + k0 + ch * 8;
    const size_t ob = (size_t)(n0 + row) * 1024 + k0 + ch * 8;
    CP_ASYNC(d,        Ah + oa);
    CP_ASYNC(d + O_AL, Al + oa);
    CP_ASYNC(d + O_BH, Bh + ob);
    CP_ASYNC(d + O_BL, Bl + ob);
}

template <int PASS>
__global__ __launch_bounds__(256, 2)
void k_mma(const __nv_bfloat16* __restrict__ Ah, const __nv_bfloat16* __restrict__ Al,
           const __nv_bfloat16* __restrict__ Bh, const __nv_bfloat16* __restrict__ Bl,
           const float* __restrict__ bqc, float* __restrict__ out) {
    extern __shared__ char sm[];
    const uint32_t sb = smem_u32(sm);
    const int tid = threadIdx.x;
    const int lane = tid & 31, wid = tid >> 5;
    const int wm = wid & 1, wn = wid >> 1;           // 2 x 4 warps, warp tile 64x32
    const int g = lane >> 2, tq = lane & 3;
    const int m0 = blockIdx.y * 128, n0 = blockIdx.x * 128;
    const int lr = lane & 15, lc = lane >> 4;

    float4 acc[4][4];
#pragma unroll
    for (int i = 0; i < 4; ++i)
#pragma unroll
        for (int j = 0; j < 4; ++j) acc[i][j] = make_float4(0.f, 0.f, 0.f, 0.f);

#pragma unroll
    for (int s = 0; s < 3; ++s) {
        fill_stage(sb + s * TS, Ah, Al, Bh, Bl, m0, n0, s * 16, tid);
        CP_COMMIT();
    }

    for (int s = 0; s < 64; ++s) {
        CP_WAIT2();
        __syncthreads();
        const uint32_t buf = sb + (uint32_t)(s & 3) * TS;

        uint32_t ah[4][4], al[4][4], bh[2][4], bl[2][4];
#pragma unroll
        for (int mt = 0; mt < 4; ++mt) {
            const int row = wm * 64 + mt * 16 + lr;
            const uint32_t off = (uint32_t)(row * 32 + ((lc ^ ((row >> 2) & 1)) * 16));
            ldsm4(ah[mt], buf + off);
            ldsm4(al[mt], buf + O_AL + off);
        }
#pragma unroll
        for (int nb = 0; nb < 2; ++nb) {
            const int row = wn * 32 + nb * 16 + lr;
            const uint32_t off = (uint32_t)(row * 32 + ((lc ^ ((row >> 2) & 1)) * 16));
            ldsm4(bh[nb], buf + O_BH + off);
            ldsm4(bl[nb], buf + O_BL + off);
        }
#pragma unroll
        for (int mt = 0; mt < 4; ++mt)
#pragma unroll
            for (int nt = 0; nt < 4; ++nt) {
                const int nb = nt >> 1, p = nt & 1;
                mma16816(acc[mt][nt], ah[mt], bh[nb][p], bh[nb][p + 2]);
                mma16816(acc[mt][nt], ah[mt], bl[nb][p], bl[nb][p + 2]);
                mma16816(acc[mt][nt], al[mt], bh[nb][p], bh[nb][p + 2]);
            }

        if (s < 61)
            fill_stage(sb + (uint32_t)((s + 3) & 3) * TS, Ah, Al, Bh, Bl,
                       m0, n0, (s + 3) * 16, tid);
        CP_COMMIT();
    }
    __syncthreads();

    if (PASS == 1) {
        const float bq = bqc[0];
        float* s_cp = (float*)sm;  // [2][128] overlay
        float cs[4][2];
#pragma unroll
        for (int nt = 0; nt < 4; ++nt) { cs[nt][0] = 0.f; cs[nt][1] = 0.f; }
#pragma unroll
        for (int mt = 0; mt < 4; ++mt) {
            const int row = m0 + wm * 64 + mt * 16 + g;
            const float ct0 = g_cterm[row], ct1 = g_cterm[row + 8];
#pragma unroll
            for (int nt = 0; nt < 4; ++nt) {
                const int col = n0 + wn * 32 + nt * 8 + tq * 2;
                const float q0 = g_qterm[col] + bq, q1 = g_qterm[col + 1] + bq;
                const float4 c = acc[mt][nt];
                const float e00 = __expf(c.x + ct0 + q0), e01 = __expf(c.y + ct0 + q1);
                const float e10 = __expf(c.z + ct1 + q0), e11 = __expf(c.w + ct1 + q1);
                uint32_t h0, h1, l0, l1;
                split4(e00, e01, e10, e11, h0, h1, l0, l1);
                const size_t o0 = (size_t)row * 1024 + col;
                const size_t o1 = (size_t)(row + 8) * 1024 + col;
                *(uint32_t*)((uint16_t*)g_eh + o0) = h0;
                *(uint32_t*)((uint16_t*)g_el + o0) = l0;
                *(uint32_t*)((uint16_t*)g_eh + o1) = h1;
                *(uint32_t*)((uint16_t*)g_el + o1) = l1;
                cs[nt][0] += e00 + e10;
                cs[nt][1] += e01 + e11;
            }
        }
#pragma unroll
        for (int nt = 0; nt < 4; ++nt)
#pragma unroll
            for (int o = 4; o < 32; o <<= 1) {
                cs[nt][0] += __shfl_xor_sync(0xffffffffu, cs[nt][0], o);
                cs[nt][1] += __shfl_xor_sync(0xffffffffu, cs[nt][1], o);
            }
        if (g == 0) {
#pragma unroll
            for (int nt = 0; nt < 4; ++nt) {
                const int col = wn * 32 + nt * 8 + tq * 2;
                s_cp[wm * 128 + col] = cs[nt][0];
                s_cp[wm * 128 + col + 1] = cs[nt][1];
            }
        }
        __syncthreads();
        if (tid < 128) {
            const float v = s_cp[tid] + s_cp[128 + tid];
            g_colpart[blockIdx.y * 1024 + n0 + tid] = v;
        }
    } else {
#pragma unroll
        for (int mt = 0; mt < 4; ++mt) {
            const int row = m0 + wm * 64 + mt * 16 + g;
#pragma unroll
            for (int nt = 0; nt < 4; ++nt) {
                const int col = n0 + wn * 32 + nt * 8 + tq * 2;
                const float4 c = acc[mt][nt];
                *(float2*)(out + (size_t)row * 1024 + col) = make_float2(c.x, c.y);
                *(float2*)(out + (size_t)(row + 8) * 1024 + col) = make_float2(c.z, c.w);
            }
        }
    }
}

// ---------------- Z_q reduction -------------------------------------------------
__global__ void k_colfin() {
    const int q = blockIdx.x * 256 + threadIdx.x;
    float s = 0.f;
#pragma unroll
    for (int i = 0; i < 64; ++i) s += g_colpart[i * 1024 + q];
    g_rz[q] = 1.f / s;
}

// ---------------- c2q softmax ---------------------------------------------------
__global__ void k_c2q() {
    const int t = threadIdx.x;
    const int lane = t & 31, wid = t >> 5;
    __shared__ float sred[32];
    __shared__ float sbc[2];
    float m = -1e30f;
    for (int c = t; c < C_LEN; c += 1024) m = fmaxf(m, g_bmax[c]);
#pragma unroll
    for (int o = 16; o; o >>= 1) m = fmaxf(m, __shfl_xor_sync(0xffffffffu, m, o));
    if (lane == 0) sred[wid] = m;
    __syncthreads();
    if (t < 32) {
        float v = sred[t];
#pragma unroll
        for (int o = 16; o; o >>= 1) v = fmaxf(v, __shfl_xor_sync(0xffffffffu, v, o));
        if (t == 0) sbc[0] = v;
    }
    __syncthreads();
    const float mm = sbc[0];
    float z = 0.f;
    for (int c = t; c < C_LEN; c += 1024) z += expf(g_bmax[c] - mm);
#pragma unroll
    for (int o = 16; o; o >>= 1) z += __shfl_xor_sync(0xffffffffu, z, o);
    __syncthreads();
    if (lane == 0) sred[wid] = z;
    __syncthreads();
    if (t < 32) {
        float v = sred[t];
#pragma unroll
        for (int o = 16; o; o >>= 1) v += __shfl_xor_sync(0xffffffffu, v, o);
        if (t == 0) sbc[1] = v;
    }
    __syncthreads();
    const float rz = 1.f / sbc[1];
    for (int c = t; c < C_LEN; c += 1024) g_w[c] = expf(g_bmax[c] - mm) * rz;
}

// ---------------- weighted column sum of H ---------------------------------------
__global__ void k_hpart(const float* __restrict__ H) {
    const int chunk = blockIdx.x, t = threadIdx.x;
    float a0 = 0.f, a1 = 0.f, a2 = 0.f, a3 = 0.f;
    const int c0 = chunk * 128;
    for (int c = c0; c < c0 + 128; ++c) {
        const float wv = g_w[c];
        const float* hr = H + (size_t)c * 1024;
        a0 = fmaf(wv, hr[t], a0);
        a1 = fmaf(wv, hr[t + 256], a1);
        a2 = fmaf(wv, hr[t + 512], a2);
        a3 = fmaf(wv, hr[t + 768], a3);
    }
    g_hpart[chunk][t] = a0;
    g_hpart[chunk][t + 256] = a1;
    g_hpart[chunk][t + 512] = a2;
    g_hpart[chunk][t + 768] = a3;
}

__global__ void k_hred() {
    const int d = blockIdx.x * 256 + threadIdx.x;
    float s = 0.f;
#pragma unroll
    for (int i = 0; i < 64; ++i) s += g_hpart[i][d];
    g_hrow[d] = s;
}

__global__ void k_bcast(float* __restrict__ out) {
    const float4 v = ((const float4*)g_hrow)[threadIdx.x];
    ((float4*)(out + (size_t)C_LEN * D_DIM))[blockIdx.x * 256 + threadIdx.x] = v;
}

// ---------------- launch ----------------------------------------------------------
extern "C" void kernel_launch(void* const* d_in, const int* in_sizes, int n_in,
                              void* d_out, int out_size) {
    const float* H   = (const float*)d_in[0];
    const float* U   = (const float*)d_in[1];
    const float* wq  = (const float*)d_in[2];
    const float* bq  = (const float*)d_in[3];
    const float* wc  = (const float*)d_in[4];
    const float* bc  = (const float*)d_in[5];
    const float* wqc = (const float*)d_in[6];
    const float* bqc = (const float*)d_in[7];
    float* out = (float*)d_out;

    static bool s_attr = false;
    if (!s_attr) {
        cudaFuncSetAttribute(k_mma<1>, cudaFuncAttributeMaxDynamicSharedMemorySize, NSTG * TS);
        cudaFuncSetAttribute(k_mma<2>, cudaFuncAttributeMaxDynamicSharedMemorySize, NSTG * TS);
        s_attr = true;
    }

    void *hh, *hl, *b1h, *b1l, *eh, *el, *b2h, *b2l;
    cudaGetSymbolAddress(&hh, g_Hh);
    cudaGetSymbolAddress(&hl, g_Hl);
    cudaGetSymbolAddress(&b1h, g_B1h);
    cudaGetSymbolAddress(&b1l, g_B1l);
    cudaGetSymbolAddress(&eh, g_eh);
    cudaGetSymbolAddress(&el, g_el);
    cudaGetSymbolAddress(&b2h, g_B2h);
    cudaGetSymbolAddress(&b2l, g_B2l);

    k_stats<<<C_LEN + Q_LEN, 256>>>(H, U, wq, bq, wc, bc);
    k_prep_h<<<C_LEN * D_DIM / 1024, 256>>>(H);
    k_prep_uw<<<Q_LEN, 256>>>(U, wqc);
    k_mma<1><<<dim3(8, 64), 256, NSTG * TS>>>((const __nv_bfloat16*)hh, (const __nv_bfloat16*)hl,
                                              (const __nv_bfloat16*)b1h, (const __nv_bfloat16*)b1l,
                                              bqc, nullptr);
    k_colfin<<<4, 256>>>();
    k_prep_ut<<<dim3(32, 32), 256>>>(U);
    k_mma<2><<<dim3(8, 64), 256, NSTG * TS>>>((const __nv_bfloat16*)eh, (const __nv_bfloat16*)el,
                                              (const __nv_bfloat16*)b2h, (const __nv_bfloat16*)b2l,
                                              bqc, out);
    k_c2q<<<1, 1024>>>();
    k_hpart<<<64, 256>>>(H);
    k_hred<<<4, 256>>>();
    k_bcast<<<C_LEN, 256>>>(out);
}